// round 5
// baseline (speedup 1.0000x reference)
#include <cuda_runtime.h>
#include <math.h>

// Problem dims (fixed per reference)
#define Lq   1024
#define Bq   4
#define Dq   512
#define Hq   8
#define DHq  64
#define DFFq 2048
#define ROWS 4096            // L*B
#define BHq  32              // B*H
#define QKV_ONE 2097152      // BH*L*DH = one of q/k/v

// -------------------- scratch (static device globals; no allocs) ------------
__device__ float g_xn  [ROWS * Dq];
__device__ float g_qkv [3 * QKV_ONE];
__device__ float g_attn[ROWS * Dq];
__device__ float g_x1  [ROWS * Dq];
__device__ float g_xn2 [ROWS * Dq];
__device__ float g_h1  [ROWS * DFFq];
__device__ float g_rmax[BHq * Lq];
__device__ float g_rinv[BHq * Lq];

// -------------------- LayerNorm: one block per row of 512 -------------------
__global__ void __launch_bounds__(128) ln_kernel(
    const float* __restrict__ x, const float* __restrict__ w,
    const float* __restrict__ b, float* __restrict__ y)
{
    const int row = blockIdx.x;
    const int t = threadIdx.x;
    const float4 v = ((const float4*)(x + (size_t)row * Dq))[t];
    float s  = v.x + v.y + v.z + v.w;
    float ss = v.x*v.x + v.y*v.y + v.z*v.z + v.w*v.w;
    #pragma unroll
    for (int o = 16; o > 0; o >>= 1) {
        s  += __shfl_xor_sync(0xffffffffu, s,  o);
        ss += __shfl_xor_sync(0xffffffffu, ss, o);
    }
    __shared__ float sh[8];
    const int wi = t >> 5, lane = t & 31;
    if (lane == 0) { sh[wi] = s; sh[4 + wi] = ss; }
    __syncthreads();
    s  = sh[0] + sh[1] + sh[2] + sh[3];
    ss = sh[4] + sh[5] + sh[6] + sh[7];
    const float mu  = s * (1.f / Dq);
    const float var = ss * (1.f / Dq) - mu * mu;
    const float rs  = rsqrtf(var + 1e-5f);
    const float4 wv = ((const float4*)w)[t];
    const float4 bv = ((const float4*)b)[t];
    float4 o;
    o.x = (v.x - mu) * rs * wv.x + bv.x;
    o.y = (v.y - mu) * rs * wv.y + bv.y;
    o.z = (v.z - mu) * rs * wv.z + bv.z;
    o.w = (v.w - mu) * rs * wv.w + bv.w;
    ((float4*)(y + (size_t)row * Dq))[t] = o;
}

// -------------------- softmax row stats: one warp per 1024-row --------------
__global__ void __launch_bounds__(256) row_stats(
    const float* __restrict__ s, float* __restrict__ rmax, float* __restrict__ rinv)
{
    const int row  = blockIdx.x * 8 + (threadIdx.x >> 5);
    const int lane = threadIdx.x & 31;
    const float4* sr = (const float4*)(s + (size_t)row * Lq);
    float4 v[8];
    float m = -1e30f;
    #pragma unroll
    for (int i = 0; i < 8; i++) {
        v[i] = sr[lane + i * 32];
        m = fmaxf(m, fmaxf(fmaxf(v[i].x, v[i].y), fmaxf(v[i].z, v[i].w)));
    }
    #pragma unroll
    for (int o = 16; o > 0; o >>= 1) m = fmaxf(m, __shfl_xor_sync(0xffffffffu, m, o));
    float sum = 0.f;
    #pragma unroll
    for (int i = 0; i < 8; i++)
        sum += expf(v[i].x - m) + expf(v[i].y - m) + expf(v[i].z - m) + expf(v[i].w - m);
    #pragma unroll
    for (int o = 16; o > 0; o >>= 1) sum += __shfl_xor_sync(0xffffffffu, sum, o);
    if (lane == 0) { rmax[row] = m; rinv[row] = 1.f / sum; }
}

// -------------------- generic tiled NT GEMM with fused epilogues ------------
// C[M,N] = A[M,K] @ B[N,K]^T  (both K-contiguous), 64x64x16 tiles, 4x4 microtile.
// MODE 0: QKV   (+bias, scatter to q/k/v [BH,L,DH])
// MODE 1: QK^T  (batched over z=bh; *0.125 + edge -> edge_out)
// MODE 2: PV    (batched; A = softmax(edge_out) applied on-the-fly; B = V loaded NN)
// MODE 3: out-proj (+bias, +residual)
// MODE 4: FFN1  (+bias, exact GELU)
// MODE 5: FFN2  (+bias, +residual)
template<int MODE>
__global__ void __launch_bounds__(256) gemm_nt(
    const float* __restrict__ A, const float* __restrict__ Bm,
    const float* __restrict__ bias, const float* __restrict__ extra,
    const float* __restrict__ rmax, const float* __restrict__ rinv,
    float* __restrict__ C, int M, int N, int K)
{
    __shared__ float As[16][68];
    __shared__ float Bs[16][68];
    const int t  = threadIdx.x;
    const int tx = t & 15, ty = t >> 4;
    const int row0 = blockIdx.y * 64, col0 = blockIdx.x * 64;
    const int z = blockIdx.z;

    const float* Ap = A;
    const float* Bp = Bm;
    if (MODE == 1) { Ap += (size_t)z * (Lq * DHq); Bp += (size_t)z * (Lq * DHq); }
    if (MODE == 2) { Ap += (size_t)z * (Lq * Lq);  Bp += (size_t)z * (Lq * DHq); }

    const int idx = t * 4;
    const int lar = idx >> 4;    // 0..63 : tile row for NT loads
    const int lac = idx & 15;    // 0,4,8,12 : k-offset
    const int lbk = idx >> 6;    // 0..15 : PV B NN load
    const int lbn = idx & 63;

    float mx = 0.f, iv = 0.f;
    if (MODE == 2) {
        const int grow = z * Lq + row0 + lar;
        mx = rmax[grow]; iv = rinv[grow];
    }

    float acc[4][4];
    #pragma unroll
    for (int i = 0; i < 4; i++)
        #pragma unroll
        for (int j = 0; j < 4; j++) acc[i][j] = 0.f;

    const float* aPtr = Ap + (size_t)(row0 + lar) * K + lac;
    for (int k0 = 0; k0 < K; k0 += 16) {
        float4 a4 = *(const float4*)(aPtr + k0);
        if (MODE == 2) {
            a4.x = expf(a4.x - mx) * iv;
            a4.y = expf(a4.y - mx) * iv;
            a4.z = expf(a4.z - mx) * iv;
            a4.w = expf(a4.w - mx) * iv;
        }
        As[lac + 0][lar] = a4.x; As[lac + 1][lar] = a4.y;
        As[lac + 2][lar] = a4.z; As[lac + 3][lar] = a4.w;
        if (MODE == 2) {
            // B = V [L, DH] row-major -> NN load: Bs[kk][n]
            float4 b4 = *(const float4*)(Bp + (size_t)(k0 + lbk) * DHq + lbn);
            *(float4*)&Bs[lbk][lbn] = b4;
        } else {
            float4 b4 = *(const float4*)(Bp + (size_t)(col0 + lar) * K + k0 + lac);
            Bs[lac + 0][lar] = b4.x; Bs[lac + 1][lar] = b4.y;
            Bs[lac + 2][lar] = b4.z; Bs[lac + 3][lar] = b4.w;
        }
        __syncthreads();
        #pragma unroll
        for (int kk = 0; kk < 16; kk++) {
            const float4 av = *(const float4*)&As[kk][ty * 4];
            const float4 bv = *(const float4*)&Bs[kk][tx * 4];
            acc[0][0] += av.x * bv.x; acc[0][1] += av.x * bv.y; acc[0][2] += av.x * bv.z; acc[0][3] += av.x * bv.w;
            acc[1][0] += av.y * bv.x; acc[1][1] += av.y * bv.y; acc[1][2] += av.y * bv.z; acc[1][3] += av.y * bv.w;
            acc[2][0] += av.z * bv.x; acc[2][1] += av.z * bv.y; acc[2][2] += av.z * bv.z; acc[2][3] += av.z * bv.w;
            acc[3][0] += av.w * bv.x; acc[3][1] += av.w * bv.y; acc[3][2] += av.w * bv.z; acc[3][3] += av.w * bv.w;
        }
        __syncthreads();
    }

    const int c0 = col0 + tx * 4;
    if (MODE == 0) {
        const float4 bb = *(const float4*)(bias + c0);
        const int which = c0 >> 9;          // 0=q,1=k,2=v
        const int cc = c0 & 511;
        const int h  = cc >> 6;
        const int dh = cc & 63;
        #pragma unroll
        for (int i = 0; i < 4; i++) {
            const int r = row0 + ty * 4 + i;
            const int l = r >> 2, b = r & 3;
            const int bh = b * Hq + h;
            float4 o = make_float4(acc[i][0] + bb.x, acc[i][1] + bb.y,
                                   acc[i][2] + bb.z, acc[i][3] + bb.w);
            *(float4*)(C + (size_t)which * QKV_ONE + ((size_t)bh * Lq + l) * DHq + dh) = o;
        }
    } else if (MODE == 1) {
        #pragma unroll
        for (int i = 0; i < 4; i++) {
            const int r = row0 + ty * 4 + i;
            const size_t off = (size_t)z * (Lq * Lq) + (size_t)r * Lq + c0;
            const float4 e = *(const float4*)(extra + off);
            float4 o = make_float4(acc[i][0] * 0.125f + e.x, acc[i][1] * 0.125f + e.y,
                                   acc[i][2] * 0.125f + e.z, acc[i][3] * 0.125f + e.w);
            *(float4*)(C + off) = o;
        }
    } else if (MODE == 2) {
        const int b = z >> 3, h = z & 7;
        #pragma unroll
        for (int i = 0; i < 4; i++) {
            const int l = row0 + ty * 4 + i;
            float4 o = make_float4(acc[i][0], acc[i][1], acc[i][2], acc[i][3]);
            *(float4*)(C + (size_t)(l * Bq + b) * Dq + h * DHq + c0) = o;
        }
    } else {
        const float4 bb = *(const float4*)(bias + c0);
        #pragma unroll
        for (int i = 0; i < 4; i++) {
            const int r = row0 + ty * 4 + i;
            float4 o = make_float4(acc[i][0] + bb.x, acc[i][1] + bb.y,
                                   acc[i][2] + bb.z, acc[i][3] + bb.w);
            if (MODE == 4) {
                o.x = 0.5f * o.x * (1.f + erff(o.x * 0.70710678118654752f));
                o.y = 0.5f * o.y * (1.f + erff(o.y * 0.70710678118654752f));
                o.z = 0.5f * o.z * (1.f + erff(o.z * 0.70710678118654752f));
                o.w = 0.5f * o.w * (1.f + erff(o.w * 0.70710678118654752f));
            } else {
                const float4 e = *(const float4*)(extra + (size_t)r * N + c0);
                o.x += e.x; o.y += e.y; o.z += e.z; o.w += e.w;
            }
            *(float4*)(C + (size_t)r * N + c0) = o;
        }
    }
}

// ----------------------------- launch ---------------------------------------
extern "C" void kernel_launch(void* const* d_in, const int* in_sizes, int n_in,
                              void* d_out, int out_size)
{
    (void)in_sizes; (void)n_in; (void)out_size;
    const float* x    = (const float*)d_in[0];
    const float* edge = (const float*)d_in[1];
    const float* inw  = (const float*)d_in[2];
    const float* inb  = (const float*)d_in[3];
    const float* outw = (const float*)d_in[4];
    const float* outb = (const float*)d_in[5];
    const float* l1w  = (const float*)d_in[6];
    const float* l1b  = (const float*)d_in[7];
    const float* l2w  = (const float*)d_in[8];
    const float* l2b  = (const float*)d_in[9];
    const float* n1w  = (const float*)d_in[10];
    const float* n1b  = (const float*)d_in[11];
    const float* n2w  = (const float*)d_in[12];
    const float* n2b  = (const float*)d_in[13];

    float *xn, *qkv, *attn, *x1, *xn2, *h1, *rmax, *rinv;
    cudaGetSymbolAddress((void**)&xn,   g_xn);
    cudaGetSymbolAddress((void**)&qkv,  g_qkv);
    cudaGetSymbolAddress((void**)&attn, g_attn);
    cudaGetSymbolAddress((void**)&x1,   g_x1);
    cudaGetSymbolAddress((void**)&xn2,  g_xn2);
    cudaGetSymbolAddress((void**)&h1,   g_h1);
    cudaGetSymbolAddress((void**)&rmax, g_rmax);
    cudaGetSymbolAddress((void**)&rinv, g_rinv);

    float* out_x    = (float*)d_out;
    float* edge_out = out_x + (size_t)ROWS * Dq;   // second output: t + edge

    // 1) LN1
    ln_kernel<<<ROWS, 128>>>(x, n1w, n1b, xn);
    // 2) QKV projection + scatter  [4096,512] x [1536,512]^T
    gemm_nt<0><<<dim3(24, 64, 1), 256>>>(xn, inw, inb, nullptr, nullptr, nullptr,
                                         qkv, ROWS, 3 * Dq, Dq);
    // 3) scores: t = qk^T/8 + edge -> edge_out (batched over 32 heads)
    gemm_nt<1><<<dim3(16, 16, BHq), 256>>>(qkv, qkv + QKV_ONE, nullptr, edge,
                                           nullptr, nullptr, edge_out, Lq, Lq, DHq);
    // 4) softmax row stats
    row_stats<<<(BHq * Lq) / 8, 256>>>(edge_out, rmax, rinv);
    // 5) attn @ V (softmax applied on the fly)
    gemm_nt<2><<<dim3(1, 16, BHq), 256>>>(edge_out, qkv + 2 * QKV_ONE, nullptr, nullptr,
                                          rmax, rinv, attn, Lq, DHq, Lq);
    // 6) out projection + residual
    gemm_nt<3><<<dim3(8, 64, 1), 256>>>(attn, outw, outb, x, nullptr, nullptr,
                                        x1, ROWS, Dq, Dq);
    // 7) LN2
    ln_kernel<<<ROWS, 128>>>(x1, n2w, n2b, xn2);
    // 8) FFN1 + GELU
    gemm_nt<4><<<dim3(32, 64, 1), 256>>>(xn2, l1w, l1b, nullptr, nullptr, nullptr,
                                         h1, ROWS, DFFq, Dq);
    // 9) FFN2 + residual -> final x output
    gemm_nt<5><<<dim3(8, 64, 1), 256>>>(h1, l2w, l2b, x1, nullptr, nullptr,
                                        out_x, ROWS, Dq, DFFq);
}

// round 7
// speedup vs baseline: 1.8200x; 1.8200x over previous
#include <cuda_runtime.h>
#include <cuda_bf16.h>
#include <math.h>
#include <stdint.h>

// ---------------- problem dims (fixed) ----------------
#define Lq   1024
#define Bq   4
#define Dq   512
#define Hq   8
#define DHq  64
#define DFFq 2048
#define ROWS 4096            // L*B
#define BHq  32              // B*H
#define QKV_ONE (BHq * Lq * DHq)   // 2097152

#define SROW 40              // smem row stride in bf16 halves (conflict-free)

// ---------------- scratch ----------------
__device__ float g_xn  [ROWS * Dq];
__device__ float g_qkv [3 * QKV_ONE];
__device__ float g_attn[ROWS * Dq];
__device__ float g_x1  [ROWS * Dq];
__device__ float g_xn2 [ROWS * Dq];
__device__ float g_h1  [ROWS * DFFq];
__device__ float g_rmax[BHq * Lq];
__device__ float g_rinv[BHq * Lq];

// ---------------- helpers ----------------
__device__ __forceinline__ void mma_bf16(float* d, const uint32_t* a, const uint32_t* b) {
    asm volatile(
        "mma.sync.aligned.m16n8k16.row.col.f32.bf16.bf16.f32 "
        "{%0,%1,%2,%3}, {%4,%5,%6,%7}, {%8,%9}, {%0,%1,%2,%3};\n"
        : "+f"(d[0]), "+f"(d[1]), "+f"(d[2]), "+f"(d[3])
        : "r"(a[0]), "r"(a[1]), "r"(a[2]), "r"(a[3]), "r"(b[0]), "r"(b[1]));
}

// float4 -> 2 hi-u32 + 2 lo-u32 (bf16x2 packs)
__device__ __forceinline__ void cvt4(float4 f, uint32_t* hi, uint32_t* lo) {
    __nv_bfloat162 h0 = __floats2bfloat162_rn(f.x, f.y);
    __nv_bfloat162 h1 = __floats2bfloat162_rn(f.z, f.w);
    float rx = f.x - __low2float(h0);
    float ry = f.y - __high2float(h0);
    float rz = f.z - __low2float(h1);
    float rw = f.w - __high2float(h1);
    __nv_bfloat162 l0 = __floats2bfloat162_rn(rx, ry);
    __nv_bfloat162 l1 = __floats2bfloat162_rn(rz, rw);
    hi[0] = *reinterpret_cast<uint32_t*>(&h0);
    hi[1] = *reinterpret_cast<uint32_t*>(&h1);
    lo[0] = *reinterpret_cast<uint32_t*>(&l0);
    lo[1] = *reinterpret_cast<uint32_t*>(&l1);
}

// ---------------- bf16-split tensor-core GEMM ----------------
// C[M,N] = A[M,K] @ B[N,K]^T, block tile 128x64, K-chunk 32, 8 warps (4Mx2N),
// warp tile 32x32 (2 m16-tiles x 4 n8-tiles). 3-pass split-bf16 emulated fp32.
// MODE 0: QKV (+bias, scatter)   MODE 1: QK^T (q pre-scaled 1/8, +edge -> edge_out)
// MODE 2: PV  (softmax on the fly; B = V transposed in smem)
// MODE 3: out-proj (+bias,+res)  MODE 4: FFN1 (+bias, GELU)  MODE 5: FFN2 (+bias,+res)
template<int MODE>
__global__ void __launch_bounds__(256) mm_gemm(
    const float* __restrict__ A, const float* __restrict__ Bm,
    const float* __restrict__ bias, const float* __restrict__ extra,
    const float* __restrict__ rmax, const float* __restrict__ rinv,
    float* __restrict__ C, int K)
{
    extern __shared__ __nv_bfloat16 sm[];
    // stage layout (halves): AH 128*40, AL 128*40, BH 64*40, BL 64*40 = 15360
    constexpr int AH_SZ = 128 * SROW;
    constexpr int BH_SZ = 64 * SROW;
    constexpr int STG   = 2 * AH_SZ + 2 * BH_SZ;

    const int t    = threadIdx.x;
    const int lane = t & 31;
    const int w    = t >> 5;
    const int g    = lane >> 2;
    const int tg   = lane & 3;
    const int warp_m = (w >> 1) * 32;
    const int warp_n = (w & 1) * 32;
    const int row0 = blockIdx.y * 128;
    const int col0 = blockIdx.x * 64;
    const int z    = blockIdx.z;

    const float* Ap = A;
    const float* Bp = Bm;
    int astride = K, bstride = K;
    if (MODE == 1) {
        Ap += (size_t)z * (Lq * DHq); Bp += (size_t)z * (Lq * DHq);
        astride = DHq; bstride = DHq;
    }
    if (MODE == 2) {
        Ap += (size_t)z * (Lq * Lq);  Bp += (size_t)z * (Lq * DHq);
        astride = Lq;
    }

    // ---- loader thread mappings ----
    const int arow = t >> 1, aseg = t & 1;           // A: 128 rows x 2 segs of 16 floats
    const int brow = t >> 2, bseg = t & 3;           // B: 64 rows x 4 segs of 8 floats
    const int vk   = t >> 3, vn0 = (t & 7) * 8;      // MODE2 B: 32 k-rows x 8 n-segs

    float mx = 0.f, iv = 0.f;
    if (MODE == 2) {
        const int grow = z * Lq + row0 + arow;
        mx = rmax[grow]; iv = rinv[grow];
    }

    float4 av[4];
    float4 bv[2];

    const int niter = K >> 5;

    auto g_load = [&](int it) {
        const int k0 = it * 32;
        const float* ap = Ap + (size_t)(row0 + arow) * astride + k0 + aseg * 16;
        #pragma unroll
        for (int i = 0; i < 4; i++) av[i] = *(const float4*)(ap + i * 4);
        if (MODE == 1) {
            #pragma unroll
            for (int i = 0; i < 4; i++) {
                av[i].x *= 0.125f; av[i].y *= 0.125f; av[i].z *= 0.125f; av[i].w *= 0.125f;
            }
        }
        if (MODE == 2) {
            #pragma unroll
            for (int i = 0; i < 4; i++) {
                av[i].x = expf(av[i].x - mx) * iv;
                av[i].y = expf(av[i].y - mx) * iv;
                av[i].z = expf(av[i].z - mx) * iv;
                av[i].w = expf(av[i].w - mx) * iv;
            }
            const float* vp = Bp + (size_t)(k0 + vk) * DHq + vn0;
            bv[0] = *(const float4*)(vp);
            bv[1] = *(const float4*)(vp + 4);
        } else {
            const float* bp = Bp + (size_t)(col0 + brow) * bstride + k0 + bseg * 8;
            bv[0] = *(const float4*)(bp);
            bv[1] = *(const float4*)(bp + 4);
        }
    };

    auto s_store = [&](int s) {
        __nv_bfloat16* AH = sm + s * STG;
        __nv_bfloat16* AL = AH + AH_SZ;
        __nv_bfloat16* BH = AL + AH_SZ;
        __nv_bfloat16* BL = BH + BH_SZ;
        // A
        {
            uint32_t hw[8], lw[8];
            #pragma unroll
            for (int i = 0; i < 4; i++) cvt4(av[i], hw + 2 * i, lw + 2 * i);
            const int off = arow * SROW + aseg * 16;
            #pragma unroll
            for (int i = 0; i < 8; i++) {
                *(uint32_t*)(AH + off + i * 2) = hw[i];
                *(uint32_t*)(AL + off + i * 2) = lw[i];
            }
        }
        // B
        if (MODE == 2) {
            const float* f = (const float*)bv;
            #pragma unroll
            for (int j = 0; j < 8; j++) {
                const float x = f[j];
                __nv_bfloat16 h = __float2bfloat16_rn(x);
                __nv_bfloat16 l = __float2bfloat16_rn(x - __bfloat162float(h));
                BH[(vn0 + j) * SROW + vk] = h;
                BL[(vn0 + j) * SROW + vk] = l;
            }
        } else {
            uint32_t hw[4], lw[4];
            cvt4(bv[0], hw, lw);
            cvt4(bv[1], hw + 2, lw + 2);
            const int off = brow * SROW + bseg * 8;
            #pragma unroll
            for (int i = 0; i < 4; i++) {
                *(uint32_t*)(BH + off + i * 2) = hw[i];
                *(uint32_t*)(BL + off + i * 2) = lw[i];
            }
        }
    };

    float c[2][4][4];
    #pragma unroll
    for (int mi = 0; mi < 2; mi++)
        #pragma unroll
        for (int ni = 0; ni < 4; ni++)
            #pragma unroll
            for (int j = 0; j < 4; j++) c[mi][ni][j] = 0.f;

    g_load(0);
    s_store(0);
    __syncthreads();

    for (int it = 0; it < niter; it++) {
        if (it + 1 < niter) g_load(it + 1);

        const int s = it & 1;
        const __nv_bfloat16* AH = sm + s * STG;
        const __nv_bfloat16* AL = AH + AH_SZ;
        const __nv_bfloat16* BH = AL + AH_SZ;
        const __nv_bfloat16* BL = BH + BH_SZ;

        #pragma unroll
        for (int kk = 0; kk < 32; kk += 16) {
            uint32_t ah[2][4], al[2][4], bh[4][2], bl[4][2];
            #pragma unroll
            for (int mi = 0; mi < 2; mi++) {
                const int rb = (warp_m + mi * 16 + g) * SROW + kk + tg * 2;
                ah[mi][0] = *(const uint32_t*)(AH + rb);
                ah[mi][1] = *(const uint32_t*)(AH + rb + 8 * SROW);
                ah[mi][2] = *(const uint32_t*)(AH + rb + 8);
                ah[mi][3] = *(const uint32_t*)(AH + rb + 8 * SROW + 8);
                al[mi][0] = *(const uint32_t*)(AL + rb);
                al[mi][1] = *(const uint32_t*)(AL + rb + 8 * SROW);
                al[mi][2] = *(const uint32_t*)(AL + rb + 8);
                al[mi][3] = *(const uint32_t*)(AL + rb + 8 * SROW + 8);
            }
            #pragma unroll
            for (int ni = 0; ni < 4; ni++) {
                const int nb = (warp_n + ni * 8 + g) * SROW + kk + tg * 2;
                bh[ni][0] = *(const uint32_t*)(BH + nb);
                bh[ni][1] = *(const uint32_t*)(BH + nb + 8);
                bl[ni][0] = *(const uint32_t*)(BL + nb);
                bl[ni][1] = *(const uint32_t*)(BL + nb + 8);
            }
            #pragma unroll
            for (int mi = 0; mi < 2; mi++)
                #pragma unroll
                for (int ni = 0; ni < 4; ni++) {
                    mma_bf16(c[mi][ni], ah[mi], bh[ni]);
                    mma_bf16(c[mi][ni], ah[mi], bl[ni]);
                    mma_bf16(c[mi][ni], al[mi], bh[ni]);
                }
        }

        if (it + 1 < niter) s_store((it + 1) & 1);
        __syncthreads();
    }

    // ---------------- epilogue ----------------
    #pragma unroll
    for (int mi = 0; mi < 2; mi++) {
        #pragma unroll
        for (int ni = 0; ni < 4; ni++) {
            const int cg = col0 + warp_n + ni * 8 + tg * 2;
            #pragma unroll
            for (int half = 0; half < 2; half++) {
                const int r = row0 + warp_m + mi * 16 + g + half * 8;
                float v0 = c[mi][ni][half * 2 + 0];
                float v1 = c[mi][ni][half * 2 + 1];

                if (MODE == 0) {
                    const float2 bb = *(const float2*)(bias + cg);
                    v0 += bb.x; v1 += bb.y;
                    const int which = cg >> 9, cc = cg & 511, h = cc >> 6, dh0 = cc & 63;
                    const int l = r >> 2, b = r & 3;
                    float* dst = C + (size_t)which * QKV_ONE +
                                 ((size_t)(b * Hq + h) * Lq + l) * DHq + dh0;
                    *(float2*)dst = make_float2(v0, v1);
                } else if (MODE == 1) {
                    const size_t off = (size_t)z * (Lq * Lq) + (size_t)r * Lq + cg;
                    const float2 e = *(const float2*)(extra + off);
                    *(float2*)(C + off) = make_float2(v0 + e.x, v1 + e.y);
                } else if (MODE == 2) {
                    const int b = z >> 3, h = z & 7;
                    float* dst = C + ((size_t)r * Bq + b) * Dq + h * DHq + cg;
                    *(float2*)dst = make_float2(v0, v1);
                } else {
                    constexpr int CN = (MODE == 4) ? DFFq : Dq;
                    const float2 bb = *(const float2*)(bias + cg);
                    v0 += bb.x; v1 += bb.y;
                    if (MODE == 4) {
                        v0 = 0.5f * v0 * (1.f + erff(v0 * 0.70710678118654752f));
                        v1 = 0.5f * v1 * (1.f + erff(v1 * 0.70710678118654752f));
                    } else {
                        const float2 e = *(const float2*)(extra + (size_t)r * CN + cg);
                        v0 += e.x; v1 += e.y;
                    }
                    *(float2*)(C + (size_t)r * CN + cg) = make_float2(v0, v1);
                }
            }
        }
    }
}

// ---------------- LayerNorm ----------------
__global__ void __launch_bounds__(128) ln_kernel(
    const float* __restrict__ x, const float* __restrict__ w,
    const float* __restrict__ b, float* __restrict__ y)
{
    const int row = blockIdx.x;
    const int t = threadIdx.x;
    const float4 v = ((const float4*)(x + (size_t)row * Dq))[t];
    float s  = v.x + v.y + v.z + v.w;
    float ss = v.x*v.x + v.y*v.y + v.z*v.z + v.w*v.w;
#pragma unroll
    for (int o = 16; o > 0; o >>= 1) {
        s  += __shfl_xor_sync(0xffffffffu, s,  o);
        ss += __shfl_xor_sync(0xffffffffu, ss, o);
    }
    __shared__ float sh[8];
    const int wi = t >> 5, lane = t & 31;
    if (lane == 0) { sh[wi] = s; sh[4 + wi] = ss; }
    __syncthreads();
    s  = sh[0] + sh[1] + sh[2] + sh[3];
    ss = sh[4] + sh[5] + sh[6] + sh[7];
    const float mu  = s * (1.f / Dq);
    const float var = ss * (1.f / Dq) - mu * mu;
    const float rs  = rsqrtf(var + 1e-5f);
    const float4 wv = ((const float4*)w)[t];
    const float4 bv = ((const float4*)b)[t];
    float4 o;
    o.x = (v.x - mu) * rs * wv.x + bv.x;
    o.y = (v.y - mu) * rs * wv.y + bv.y;
    o.z = (v.z - mu) * rs * wv.z + bv.z;
    o.w = (v.w - mu) * rs * wv.w + bv.w;
    ((float4*)(y + (size_t)row * Dq))[t] = o;
}

// ---------------- softmax row stats ----------------
__global__ void __launch_bounds__(256) row_stats(
    const float* __restrict__ s, float* __restrict__ rmax, float* __restrict__ rinv)
{
    const int row  = blockIdx.x * 8 + (threadIdx.x >> 5);
    const int lane = threadIdx.x & 31;
    const float4* sr = (const float4*)(s + (size_t)row * Lq);
    float4 v[8];
    float m = -1e30f;
#pragma unroll
    for (int i = 0; i < 8; i++) {
        v[i] = sr[lane + i * 32];
        m = fmaxf(m, fmaxf(fmaxf(v[i].x, v[i].y), fmaxf(v[i].z, v[i].w)));
    }
#pragma unroll
    for (int o = 16; o > 0; o >>= 1) m = fmaxf(m, __shfl_xor_sync(0xffffffffu, m, o));
    float sum = 0.f;
#pragma unroll
    for (int i = 0; i < 8; i++)
        sum += expf(v[i].x - m) + expf(v[i].y - m) + expf(v[i].z - m) + expf(v[i].w - m);
#pragma unroll
    for (int o = 16; o > 0; o >>= 1) sum += __shfl_xor_sync(0xffffffffu, sum, o);
    if (lane == 0) { rmax[row] = m; rinv[row] = 1.f / sum; }
}

// ---------------- launch ----------------
extern "C" void kernel_launch(void* const* d_in, const int* in_sizes, int n_in,
                              void* d_out, int out_size)
{
    (void)in_sizes; (void)n_in; (void)out_size;
    const float* x    = (const float*)d_in[0];
    const float* edge = (const float*)d_in[1];
    const float* inw  = (const float*)d_in[2];
    const float* inb  = (const float*)d_in[3];
    const float* outw = (const float*)d_in[4];
    const float* outb = (const float*)d_in[5];
    const float* l1w  = (const float*)d_in[6];
    const float* l1b  = (const float*)d_in[7];
    const float* l2w  = (const float*)d_in[8];
    const float* l2b  = (const float*)d_in[9];
    const float* n1w  = (const float*)d_in[10];
    const float* n1b  = (const float*)d_in[11];
    const float* n2w  = (const float*)d_in[12];
    const float* n2b  = (const float*)d_in[13];

    float *xn, *qkv, *attn, *x1, *xn2, *h1, *rmax, *rinv;
    cudaGetSymbolAddress((void**)&xn,   g_xn);
    cudaGetSymbolAddress((void**)&qkv,  g_qkv);
    cudaGetSymbolAddress((void**)&attn, g_attn);
    cudaGetSymbolAddress((void**)&x1,   g_x1);
    cudaGetSymbolAddress((void**)&xn2,  g_xn2);
    cudaGetSymbolAddress((void**)&h1,   g_h1);
    cudaGetSymbolAddress((void**)&rmax, g_rmax);
    cudaGetSymbolAddress((void**)&rinv, g_rinv);

    float* out_x    = (float*)d_out;
    float* edge_out = out_x + (size_t)ROWS * Dq;

    const int SMEM = 2 * (2 * 128 * SROW + 2 * 64 * SROW) * (int)sizeof(__nv_bfloat16); // 61440
    cudaFuncSetAttribute(mm_gemm<0>, cudaFuncAttributeMaxDynamicSharedMemorySize, SMEM);
    cudaFuncSetAttribute(mm_gemm<1>, cudaFuncAttributeMaxDynamicSharedMemorySize, SMEM);
    cudaFuncSetAttribute(mm_gemm<2>, cudaFuncAttributeMaxDynamicSharedMemorySize, SMEM);
    cudaFuncSetAttribute(mm_gemm<3>, cudaFuncAttributeMaxDynamicSharedMemorySize, SMEM);
    cudaFuncSetAttribute(mm_gemm<4>, cudaFuncAttributeMaxDynamicSharedMemorySize, SMEM);
    cudaFuncSetAttribute(mm_gemm<5>, cudaFuncAttributeMaxDynamicSharedMemorySize, SMEM);

    // 1) LN1
    ln_kernel<<<ROWS, 128>>>(x, n1w, n1b, xn);
    // 2) QKV projection + scatter: [4096,1536]
    mm_gemm<0><<<dim3(24, 32, 1), 256, SMEM>>>(xn, inw, inb, nullptr, nullptr, nullptr, qkv, Dq);
    // 3) scores: t = (q/8)@k^T + edge -> edge_out
    mm_gemm<1><<<dim3(16, 8, BHq), 256, SMEM>>>(qkv, qkv + QKV_ONE, nullptr, edge,
                                                nullptr, nullptr, edge_out, DHq);
    // 4) softmax row stats
    row_stats<<<(BHq * Lq) / 8, 256>>>(edge_out, rmax, rinv);
    // 5) attn @ V (softmax on the fly, V transposed in smem)
    mm_gemm<2><<<dim3(1, 8, BHq), 256, SMEM>>>(edge_out, qkv + 2 * QKV_ONE, nullptr, nullptr,
                                               rmax, rinv, attn, Lq);
    // 6) out projection + residual
    mm_gemm<3><<<dim3(8, 32, 1), 256, SMEM>>>(attn, outw, outb, x, nullptr, nullptr, x1, Dq);
    // 7) LN2
    ln_kernel<<<ROWS, 128>>>(x1, n2w, n2b, xn2);
    // 8) FFN1 + GELU
    mm_gemm<4><<<dim3(32, 32, 1), 256, SMEM>>>(xn2, l1w, l1b, nullptr, nullptr, nullptr, h1, Dq);
    // 9) FFN2 + residual -> final x output
    mm_gemm<5><<<dim3(8, 32, 1), 256, SMEM>>>(h1, l2w, l2b, x1, nullptr, nullptr, out_x, DFFq);
}

// round 9
// speedup vs baseline: 1.9921x; 1.0945x over previous
#include <cuda_runtime.h>
#include <cuda_bf16.h>
#include <math.h>
#include <stdint.h>

// ---------------- problem dims (fixed) ----------------
#define Lq   1024
#define Bq   4
#define Dq   512
#define Hq   8
#define DHq  64
#define DFFq 2048
#define ROWS 4096
#define BHq  32
#define QKV_ONE (BHq * Lq * DHq)   // 2097152
#define SROW 40                    // smem row stride in halves (conflict-free)

// ---------------- persistent scratch: hi/lo bf16 planes + fp32 ----------------
__device__ __nv_bfloat16 g_xn_h [ROWS * Dq],  g_xn_l [ROWS * Dq];
__device__ __nv_bfloat16 g_xn2_h[ROWS * Dq],  g_xn2_l[ROWS * Dq];
__device__ __nv_bfloat16 g_q_h[QKV_ONE], g_q_l[QKV_ONE];
__device__ __nv_bfloat16 g_k_h[QKV_ONE], g_k_l[QKV_ONE];
__device__ float         g_v  [QKV_ONE];
__device__ __nv_bfloat16 g_at_h[ROWS * Dq],  g_at_l[ROWS * Dq];
__device__ float         g_x1 [ROWS * Dq];
__device__ __nv_bfloat16 g_h1_h[ROWS * DFFq], g_h1_l[ROWS * DFFq];
__device__ __nv_bfloat16 g_w1h[1536 * 512], g_w1l[1536 * 512];   // in_proj_w
__device__ __nv_bfloat16 g_w2h[512 * 512],  g_w2l[512 * 512];    // out_proj_w
__device__ __nv_bfloat16 g_w3h[2048 * 512], g_w3l[2048 * 512];   // lin1_w
__device__ __nv_bfloat16 g_w4h[512 * 2048], g_w4l[512 * 2048];   // lin2_w
__device__ float g_rmax[BHq * Lq], g_rinv[BHq * Lq];

// ---------------- helpers ----------------
__device__ __forceinline__ uint32_t smem_u32(const void* p) {
    uint32_t a;
    asm("{ .reg .u64 t; cvta.to.shared.u64 t, %1; cvt.u32.u64 %0, t; }" : "=r"(a) : "l"(p));
    return a;
}
__device__ __forceinline__ void cpa16(uint32_t s, const void* g) {
    asm volatile("cp.async.cg.shared.global [%0], [%1], 16;" :: "r"(s), "l"(g) : "memory");
}
__device__ __forceinline__ void mma_bf16(float* d, const uint32_t* a, const uint32_t* b) {
    asm volatile(
        "mma.sync.aligned.m16n8k16.row.col.f32.bf16.bf16.f32 "
        "{%0,%1,%2,%3}, {%4,%5,%6,%7}, {%8,%9}, {%0,%1,%2,%3};\n"
        : "+f"(d[0]), "+f"(d[1]), "+f"(d[2]), "+f"(d[3])
        : "r"(a[0]), "r"(a[1]), "r"(a[2]), "r"(a[3]), "r"(b[0]), "r"(b[1]));
}
// split two floats into hi/lo bf16x2 packs
__device__ __forceinline__ void split2(float v0, float v1, uint32_t& hb, uint32_t& lb) {
    __nv_bfloat162 hh = __floats2bfloat162_rn(v0, v1);
    __nv_bfloat162 ll = __floats2bfloat162_rn(v0 - __low2float(hh), v1 - __high2float(hh));
    hb = *reinterpret_cast<uint32_t*>(&hh);
    lb = *reinterpret_cast<uint32_t*>(&ll);
}

// ---------------- fp32 -> hi/lo plane converter (weights) ----------------
__global__ void __launch_bounds__(256) to_planes(
    const float* __restrict__ s, __nv_bfloat16* __restrict__ h,
    __nv_bfloat16* __restrict__ l, int n4)
{
    const int i = blockIdx.x * 256 + threadIdx.x;
    if (i >= n4) return;
    const float4 v = ((const float4*)s)[i];
    uint32_t h0, l0, h1, l1;
    split2(v.x, v.y, h0, l0);
    split2(v.z, v.w, h1, l1);
    ((uint32_t*)h)[i * 2]     = h0;
    ((uint32_t*)h)[i * 2 + 1] = h1;
    ((uint32_t*)l)[i * 2]     = l0;
    ((uint32_t*)l)[i * 2 + 1] = l1;
}

// ---------------- plane GEMM: C[M,N] = A @ B^T, 3-pass split-bf16 ----------------
// block 128x128, K-chunk 32, 8 warps (4m x 2n), warp tile 32x64, cp.async 2-stage.
// MODE 0: QKV (+bias; q,k -> planes; v -> fp32)
// MODE 1: QK^T (z=head; acc*0.125 + edge -> edge_out fp32)
// MODE 3: out-proj (+bias, +residual -> fp32)
// MODE 4: FFN1 (+bias, GELU -> planes)
// MODE 5: FFN2 (+bias, +residual -> fp32)
template<int MODE>
__global__ void __launch_bounds__(256, 2) pg(
    const __nv_bfloat16* __restrict__ Ah, const __nv_bfloat16* __restrict__ Al,
    const __nv_bfloat16* __restrict__ Bh, const __nv_bfloat16* __restrict__ Bl,
    const float* __restrict__ bias, const float* __restrict__ extra,
    float* __restrict__ Cf,
    __nv_bfloat16* __restrict__ P0h, __nv_bfloat16* __restrict__ P0l,
    __nv_bfloat16* __restrict__ P1h, __nv_bfloat16* __restrict__ P1l,
    int K, int astr, int bstr)
{
    extern __shared__ __nv_bfloat16 sm[];
    constexpr int PL  = 128 * SROW;     // halves per plane per stage
    constexpr int STG = 4 * PL;         // AH AL BH BL

    const int t = threadIdx.x, lane = t & 31, w = t >> 5;
    const int g = lane >> 2, tg = lane & 3;
    const int warp_m = (w >> 1) * 32, warp_n = (w & 1) * 64;
    const int row0 = blockIdx.y * 128, col0 = blockIdx.x * 128, z = blockIdx.z;

    const __nv_bfloat16* pAh = Ah; const __nv_bfloat16* pAl = Al;
    const __nv_bfloat16* pBh = Bh; const __nv_bfloat16* pBl = Bl;
    if (MODE == 1) {
        const size_t off = (size_t)z * Lq * DHq;
        pAh += off; pAl += off; pBh += off; pBl += off;
    }

    const int lrow = t >> 1, lseg = (t & 1) * 16;   // halves
    const uint32_t sbase = smem_u32(sm);
    const uint32_t srow  = sbase + (uint32_t)(lrow * SROW + lseg) * 2;
    const int niter = K >> 5;

    auto issue = [&](int it) {
        if (it < niter) {
            const int k0 = it * 32;
            const size_t ao = (size_t)(row0 + lrow) * astr + k0 + lseg;
            const size_t bo = (size_t)(col0 + lrow) * bstr + k0 + lseg;
            uint32_t d = srow + (uint32_t)((it & 1) * STG) * 2;
            cpa16(d, pAh + ao);            cpa16(d + 16, pAh + ao + 8);
            d += PL * 2;
            cpa16(d, pAl + ao);            cpa16(d + 16, pAl + ao + 8);
            d += PL * 2;
            cpa16(d, pBh + bo);            cpa16(d + 16, pBh + bo + 8);
            d += PL * 2;
            cpa16(d, pBl + bo);            cpa16(d + 16, pBl + bo + 8);
            asm volatile("cp.async.commit_group;" ::: "memory");
        }
    };

    float c[2][8][4];
    #pragma unroll
    for (int i = 0; i < 2; i++)
        #pragma unroll
        for (int j = 0; j < 8; j++)
            #pragma unroll
            for (int q2 = 0; q2 < 4; q2++) c[i][j][q2] = 0.f;

    issue(0); issue(1);

    for (int it = 0; it < niter; it++) {
        if (it + 2 <= niter) asm volatile("cp.async.wait_group 1;" ::: "memory");
        else                 asm volatile("cp.async.wait_group 0;" ::: "memory");
        __syncthreads();

        const __nv_bfloat16* AH = sm + (it & 1) * STG;
        const __nv_bfloat16* AL = AH + PL;
        const __nv_bfloat16* BH = AL + PL;
        const __nv_bfloat16* BL = BH + PL;

        #pragma unroll
        for (int kk = 0; kk < 32; kk += 16) {
            uint32_t ah[2][4], al[2][4];
            #pragma unroll
            for (int mi = 0; mi < 2; mi++) {
                const int rb = (warp_m + mi * 16 + g) * SROW + kk + tg * 2;
                ah[mi][0] = *(const uint32_t*)(AH + rb);
                ah[mi][1] = *(const uint32_t*)(AH + rb + 8 * SROW);
                ah[mi][2] = *(const uint32_t*)(AH + rb + 8);
                ah[mi][3] = *(const uint32_t*)(AH + rb + 8 * SROW + 8);
                al[mi][0] = *(const uint32_t*)(AL + rb);
                al[mi][1] = *(const uint32_t*)(AL + rb + 8 * SROW);
                al[mi][2] = *(const uint32_t*)(AL + rb + 8);
                al[mi][3] = *(const uint32_t*)(AL + rb + 8 * SROW + 8);
            }
            #pragma unroll
            for (int ni = 0; ni < 8; ni++) {
                const int nb = (warp_n + ni * 8 + g) * SROW + kk + tg * 2;
                uint32_t bh[2], bl[2];
                bh[0] = *(const uint32_t*)(BH + nb);
                bh[1] = *(const uint32_t*)(BH + nb + 8);
                bl[0] = *(const uint32_t*)(BL + nb);
                bl[1] = *(const uint32_t*)(BL + nb + 8);
                #pragma unroll
                for (int mi = 0; mi < 2; mi++) {
                    mma_bf16(c[mi][ni], ah[mi], bh);
                    mma_bf16(c[mi][ni], ah[mi], bl);
                    mma_bf16(c[mi][ni], al[mi], bh);
                }
            }
        }
        __syncthreads();
        issue(it + 2);
    }

    // ---------------- epilogue ----------------
    #pragma unroll
    for (int mi = 0; mi < 2; mi++)
    #pragma unroll
    for (int ni = 0; ni < 8; ni++) {
        const int cg = col0 + warp_n + ni * 8 + tg * 2;
        #pragma unroll
        for (int hf = 0; hf < 2; hf++) {
            const int r = row0 + warp_m + mi * 16 + g + hf * 8;
            float v0 = c[mi][ni][hf * 2 + 0];
            float v1 = c[mi][ni][hf * 2 + 1];

            if (MODE == 1) {
                const size_t off = (size_t)z * (Lq * Lq) + (size_t)r * Lq + cg;
                const float2 e = *(const float2*)(extra + off);
                *(float2*)(Cf + off) = make_float2(v0 * 0.125f + e.x, v1 * 0.125f + e.y);
            } else if (MODE == 0) {
                const float2 bb = *(const float2*)(bias + cg);
                v0 += bb.x; v1 += bb.y;
                const int which = cg >> 9, cc = cg & 511, h = cc >> 6, dh0 = cc & 63;
                const int l = r >> 2, b = r & 3;
                const size_t o = ((size_t)(b * Hq + h) * Lq + l) * DHq + dh0;
                if (which == 2) {
                    *(float2*)(Cf + o) = make_float2(v0, v1);
                } else {
                    uint32_t hb, lb; split2(v0, v1, hb, lb);
                    __nv_bfloat16* dh_ = (which == 0) ? P0h : P1h;
                    __nv_bfloat16* dl_ = (which == 0) ? P0l : P1l;
                    *(uint32_t*)(dh_ + o) = hb;
                    *(uint32_t*)(dl_ + o) = lb;
                }
            } else if (MODE == 4) {
                const float2 bb = *(const float2*)(bias + cg);
                v0 += bb.x; v1 += bb.y;
                v0 = 0.5f * v0 * (1.f + erff(v0 * 0.70710678118654752f));
                v1 = 0.5f * v1 * (1.f + erff(v1 * 0.70710678118654752f));
                const size_t o = (size_t)r * DFFq + cg;
                uint32_t hb, lb; split2(v0, v1, hb, lb);
                *(uint32_t*)(P0h + o) = hb;
                *(uint32_t*)(P0l + o) = lb;
            } else {   // MODE 3 / 5: bias + residual -> fp32
                const float2 bb = *(const float2*)(bias + cg);
                const size_t o = (size_t)r * Dq + cg;
                const float2 e = *(const float2*)(extra + o);
                *(float2*)(Cf + o) = make_float2(v0 + bb.x + e.x, v1 + bb.y + e.y);
            }
        }
    }
}

// ---------------- PV GEMM (softmax on the fly; fp32 inputs) -> attn planes ----------
__global__ void __launch_bounds__(256) pv_gemm(
    const float* __restrict__ S, const float* __restrict__ V,
    const float* __restrict__ rmax, const float* __restrict__ rinv,
    __nv_bfloat16* __restrict__ Oh, __nv_bfloat16* __restrict__ Ol)
{
    extern __shared__ __nv_bfloat16 sm[];
    constexpr int AH_SZ = 128 * SROW;
    constexpr int BH_SZ = 64 * SROW;
    constexpr int STG   = 2 * AH_SZ + 2 * BH_SZ;

    const int t = threadIdx.x, lane = t & 31, w = t >> 5;
    const int g = lane >> 2, tg = lane & 3;
    const int warp_m = (w >> 1) * 32, warp_n = (w & 1) * 32;
    const int row0 = blockIdx.y * 128, z = blockIdx.z;

    const float* Ap = S + (size_t)z * (Lq * Lq);
    const float* Bp = V + (size_t)z * (Lq * DHq);

    const int arow = t >> 1, aseg = t & 1;
    const int vk = t >> 3, vn0 = (t & 7) * 8;

    const int grow = z * Lq + row0 + arow;
    const float mx = rmax[grow], iv = rinv[grow];

    float4 av[4], bv[2];
    const int niter = Lq >> 5;   // 32

    auto g_load = [&](int it) {
        const int k0 = it * 32;
        const float* ap = Ap + (size_t)(row0 + arow) * Lq + k0 + aseg * 16;
        #pragma unroll
        for (int i = 0; i < 4; i++) {
            av[i] = *(const float4*)(ap + i * 4);
            av[i].x = expf(av[i].x - mx) * iv;
            av[i].y = expf(av[i].y - mx) * iv;
            av[i].z = expf(av[i].z - mx) * iv;
            av[i].w = expf(av[i].w - mx) * iv;
        }
        const float* vp = Bp + (size_t)(k0 + vk) * DHq + vn0;
        bv[0] = *(const float4*)(vp);
        bv[1] = *(const float4*)(vp + 4);
    };

    auto s_store = [&](int s) {
        __nv_bfloat16* AH = sm + s * STG;
        __nv_bfloat16* AL = AH + AH_SZ;
        __nv_bfloat16* BH = AL + AH_SZ;
        __nv_bfloat16* BL = BH + BH_SZ;
        {
            uint32_t hw[8], lw[8];
            #pragma unroll
            for (int i = 0; i < 4; i++) {
                split2(av[i].x, av[i].y, hw[2*i],   lw[2*i]);
                split2(av[i].z, av[i].w, hw[2*i+1], lw[2*i+1]);
            }
            const int off = arow * SROW + aseg * 16;
            #pragma unroll
            for (int i = 0; i < 8; i++) {
                *(uint32_t*)(AH + off + i * 2) = hw[i];
                *(uint32_t*)(AL + off + i * 2) = lw[i];
            }
        }
        {
            const float* f = (const float*)bv;
            #pragma unroll
            for (int j = 0; j < 8; j++) {
                const float x = f[j];
                __nv_bfloat16 h = __float2bfloat16_rn(x);
                __nv_bfloat16 l = __float2bfloat16_rn(x - __bfloat162float(h));
                BH[(vn0 + j) * SROW + vk] = h;
                BL[(vn0 + j) * SROW + vk] = l;
            }
        }
    };

    float c[2][4][4];
    #pragma unroll
    for (int mi = 0; mi < 2; mi++)
        #pragma unroll
        for (int ni = 0; ni < 4; ni++)
            #pragma unroll
            for (int j = 0; j < 4; j++) c[mi][ni][j] = 0.f;

    g_load(0); s_store(0); __syncthreads();

    for (int it = 0; it < niter; it++) {
        if (it + 1 < niter) g_load(it + 1);
        const int s = it & 1;
        const __nv_bfloat16* AH = sm + s * STG;
        const __nv_bfloat16* AL = AH + AH_SZ;
        const __nv_bfloat16* BH = AL + AH_SZ;
        const __nv_bfloat16* BL = BH + BH_SZ;

        #pragma unroll
        for (int kk = 0; kk < 32; kk += 16) {
            uint32_t ah[2][4], al[2][4], bh[4][2], bl[4][2];
            #pragma unroll
            for (int mi = 0; mi < 2; mi++) {
                const int rb = (warp_m + mi * 16 + g) * SROW + kk + tg * 2;
                ah[mi][0] = *(const uint32_t*)(AH + rb);
                ah[mi][1] = *(const uint32_t*)(AH + rb + 8 * SROW);
                ah[mi][2] = *(const uint32_t*)(AH + rb + 8);
                ah[mi][3] = *(const uint32_t*)(AH + rb + 8 * SROW + 8);
                al[mi][0] = *(const uint32_t*)(AL + rb);
                al[mi][1] = *(const uint32_t*)(AL + rb + 8 * SROW);
                al[mi][2] = *(const uint32_t*)(AL + rb + 8);
                al[mi][3] = *(const uint32_t*)(AL + rb + 8 * SROW + 8);
            }
            #pragma unroll
            for (int ni = 0; ni < 4; ni++) {
                const int nb = (warp_n + ni * 8 + g) * SROW + kk + tg * 2;
                bh[ni][0] = *(const uint32_t*)(BH + nb);
                bh[ni][1] = *(const uint32_t*)(BH + nb + 8);
                bl[ni][0] = *(const uint32_t*)(BL + nb);
                bl[ni][1] = *(const uint32_t*)(BL + nb + 8);
            }
            #pragma unroll
            for (int mi = 0; mi < 2; mi++)
                #pragma unroll
                for (int ni = 0; ni < 4; ni++) {
                    mma_bf16(c[mi][ni], ah[mi], bh[ni]);
                    mma_bf16(c[mi][ni], ah[mi], bl[ni]);
                    mma_bf16(c[mi][ni], al[mi], bh[ni]);
                }
        }
        if (it + 1 < niter) s_store((it + 1) & 1);
        __syncthreads();
    }

    // epilogue -> attn hi/lo planes, layout [l][b][h*64+dh]
    const int b = z >> 3, h = z & 7;
    #pragma unroll
    for (int mi = 0; mi < 2; mi++)
    #pragma unroll
    for (int ni = 0; ni < 4; ni++) {
        const int cg = warp_n + ni * 8 + tg * 2;
        #pragma unroll
        for (int hf = 0; hf < 2; hf++) {
            const int r = row0 + warp_m + mi * 16 + g + hf * 8;
            const float v0 = c[mi][ni][hf * 2 + 0];
            const float v1 = c[mi][ni][hf * 2 + 1];
            const size_t o = ((size_t)r * Bq + b) * Dq + h * DHq + cg;
            uint32_t hb, lb; split2(v0, v1, hb, lb);
            *(uint32_t*)(Oh + o) = hb;
            *(uint32_t*)(Ol + o) = lb;
        }
    }
}

// ---------------- LayerNorm -> hi/lo planes ----------------
__global__ void __launch_bounds__(128) ln_kernel(
    const float* __restrict__ x, const float* __restrict__ w,
    const float* __restrict__ b, __nv_bfloat16* __restrict__ yh,
    __nv_bfloat16* __restrict__ yl)
{
    const int row = blockIdx.x;
    const int t = threadIdx.x;
    const float4 v = ((const float4*)(x + (size_t)row * Dq))[t];
    float s  = v.x + v.y + v.z + v.w;
    float ss = v.x*v.x + v.y*v.y + v.z*v.z + v.w*v.w;
#pragma unroll
    for (int o = 16; o > 0; o >>= 1) {
        s  += __shfl_xor_sync(0xffffffffu, s,  o);
        ss += __shfl_xor_sync(0xffffffffu, ss, o);
    }
    __shared__ float sh[8];
    const int wi = t >> 5, lane = t & 31;
    if (lane == 0) { sh[wi] = s; sh[4 + wi] = ss; }
    __syncthreads();
    s  = sh[0] + sh[1] + sh[2] + sh[3];
    ss = sh[4] + sh[5] + sh[6] + sh[7];
    const float mu  = s * (1.f / Dq);
    const float var = ss * (1.f / Dq) - mu * mu;
    const float rs  = rsqrtf(var + 1e-5f);
    const float4 wv = ((const float4*)w)[t];
    const float4 bv = ((const float4*)b)[t];
    const float o0 = (v.x - mu) * rs * wv.x + bv.x;
    const float o1 = (v.y - mu) * rs * wv.y + bv.y;
    const float o2 = (v.z - mu) * rs * wv.z + bv.z;
    const float o3 = (v.w - mu) * rs * wv.w + bv.w;
    uint32_t h0, l0, h1, l1;
    split2(o0, o1, h0, l0);
    split2(o2, o3, h1, l1);
    uint32_t* ph = (uint32_t*)(yh + (size_t)row * Dq);
    uint32_t* pl = (uint32_t*)(yl + (size_t)row * Dq);
    ph[t * 2] = h0; ph[t * 2 + 1] = h1;
    pl[t * 2] = l0; pl[t * 2 + 1] = l1;
}

// ---------------- softmax row stats ----------------
__global__ void __launch_bounds__(256) row_stats(
    const float* __restrict__ s, float* __restrict__ rmax, float* __restrict__ rinv)
{
    const int row  = blockIdx.x * 8 + (threadIdx.x >> 5);
    const int lane = threadIdx.x & 31;
    const float4* sr = (const float4*)(s + (size_t)row * Lq);
    float4 v[8];
    float m = -1e30f;
#pragma unroll
    for (int i = 0; i < 8; i++) {
        v[i] = sr[lane + i * 32];
        m = fmaxf(m, fmaxf(fmaxf(v[i].x, v[i].y), fmaxf(v[i].z, v[i].w)));
    }
#pragma unroll
    for (int o = 16; o > 0; o >>= 1) m = fmaxf(m, __shfl_xor_sync(0xffffffffu, m, o));
    float sum = 0.f;
#pragma unroll
    for (int i = 0; i < 8; i++)
        sum += expf(v[i].x - m) + expf(v[i].y - m) + expf(v[i].z - m) + expf(v[i].w - m);
#pragma unroll
    for (int o = 16; o > 0; o >>= 1) sum += __shfl_xor_sync(0xffffffffu, sum, o);
    if (lane == 0) { rmax[row] = m; rinv[row] = 1.f / sum; }
}

// ---------------- launch ----------------
extern "C" void kernel_launch(void* const* d_in, const int* in_sizes, int n_in,
                              void* d_out, int out_size)
{
    (void)in_sizes; (void)n_in; (void)out_size;
    const float* x    = (const float*)d_in[0];
    const float* edge = (const float*)d_in[1];
    const float* inw  = (const float*)d_in[2];
    const float* inb  = (const float*)d_in[3];
    const float* outw = (const float*)d_in[4];
    const float* outb = (const float*)d_in[5];
    const float* l1w  = (const float*)d_in[6];
    const float* l1b  = (const float*)d_in[7];
    const float* l2w  = (const float*)d_in[8];
    const float* l2b  = (const float*)d_in[9];
    const float* n1w  = (const float*)d_in[10];
    const float* n1b  = (const float*)d_in[11];
    const float* n2w  = (const float*)d_in[12];
    const float* n2b  = (const float*)d_in[13];

    __nv_bfloat16 *xnh,*xnl,*xn2h,*xn2l,*qh,*ql,*kh,*kl,*ath,*atl,*h1h,*h1l;
    __nv_bfloat16 *w1h,*w1l,*w2h,*w2l,*w3h,*w3l,*w4h,*w4l;
    float *v, *x1, *rmax, *rinv;
    cudaGetSymbolAddress((void**)&xnh,  g_xn_h);   cudaGetSymbolAddress((void**)&xnl,  g_xn_l);
    cudaGetSymbolAddress((void**)&xn2h, g_xn2_h);  cudaGetSymbolAddress((void**)&xn2l, g_xn2_l);
    cudaGetSymbolAddress((void**)&qh,   g_q_h);    cudaGetSymbolAddress((void**)&ql,   g_q_l);
    cudaGetSymbolAddress((void**)&kh,   g_k_h);    cudaGetSymbolAddress((void**)&kl,   g_k_l);
    cudaGetSymbolAddress((void**)&ath,  g_at_h);   cudaGetSymbolAddress((void**)&atl,  g_at_l);
    cudaGetSymbolAddress((void**)&h1h,  g_h1_h);   cudaGetSymbolAddress((void**)&h1l,  g_h1_l);
    cudaGetSymbolAddress((void**)&w1h,  g_w1h);    cudaGetSymbolAddress((void**)&w1l,  g_w1l);
    cudaGetSymbolAddress((void**)&w2h,  g_w2h);    cudaGetSymbolAddress((void**)&w2l,  g_w2l);
    cudaGetSymbolAddress((void**)&w3h,  g_w3h);    cudaGetSymbolAddress((void**)&w3l,  g_w3l);
    cudaGetSymbolAddress((void**)&w4h,  g_w4h);    cudaGetSymbolAddress((void**)&w4l,  g_w4l);
    cudaGetSymbolAddress((void**)&v,    g_v);
    cudaGetSymbolAddress((void**)&x1,   g_x1);
    cudaGetSymbolAddress((void**)&rmax, g_rmax);   cudaGetSymbolAddress((void**)&rinv, g_rinv);

    float* out_x    = (float*)d_out;
    float* edge_out = out_x + (size_t)ROWS * Dq;

    const int PG_SMEM = 2 * 4 * 128 * SROW * (int)sizeof(__nv_bfloat16);          // 81920
    const int PV_SMEM = 2 * (2 * 128 * SROW + 2 * 64 * SROW) * (int)sizeof(__nv_bfloat16); // 61440
    cudaFuncSetAttribute(pg<0>, cudaFuncAttributeMaxDynamicSharedMemorySize, PG_SMEM);
    cudaFuncSetAttribute(pg<1>, cudaFuncAttributeMaxDynamicSharedMemorySize, PG_SMEM);
    cudaFuncSetAttribute(pg<3>, cudaFuncAttributeMaxDynamicSharedMemorySize, PG_SMEM);
    cudaFuncSetAttribute(pg<4>, cudaFuncAttributeMaxDynamicSharedMemorySize, PG_SMEM);
    cudaFuncSetAttribute(pg<5>, cudaFuncAttributeMaxDynamicSharedMemorySize, PG_SMEM);
    cudaFuncSetAttribute(pv_gemm, cudaFuncAttributeMaxDynamicSharedMemorySize, PV_SMEM);

    // 0) split weights into planes
    to_planes<<<768, 256>>>(inw,  w1h, w1l, 1536 * 512 / 4);
    to_planes<<<256, 256>>>(outw, w2h, w2l, 512 * 512 / 4);
    to_planes<<<1024, 256>>>(l1w, w3h, w3l, 2048 * 512 / 4);
    to_planes<<<1024, 256>>>(l2w, w4h, w4l, 512 * 2048 / 4);
    // 1) LN1 -> xn planes
    ln_kernel<<<ROWS, 128>>>(x, n1w, n1b, xnh, xnl);
    // 2) QKV: q,k -> planes, v -> fp32
    pg<0><<<dim3(12, 32, 1), 256, PG_SMEM>>>(xnh, xnl, w1h, w1l, inb, nullptr,
                                             v, qh, ql, kh, kl, Dq, Dq, Dq);
    // 3) scores: t = (q@k^T)/8 + edge -> edge_out
    pg<1><<<dim3(8, 8, BHq), 256, PG_SMEM>>>(qh, ql, kh, kl, nullptr, edge,
                                             edge_out, nullptr, nullptr, nullptr, nullptr,
                                             DHq, DHq, DHq);
    // 4) softmax row stats
    row_stats<<<(BHq * Lq) / 8, 256>>>(edge_out, rmax, rinv);
    // 5) attn @ V -> attn planes
    pv_gemm<<<dim3(1, 8, BHq), 256, PV_SMEM>>>(edge_out, v, rmax, rinv, ath, atl);
    // 6) out projection + residual -> x1 fp32
    pg<3><<<dim3(4, 32, 1), 256, PG_SMEM>>>(ath, atl, w2h, w2l, outb, x,
                                            x1, nullptr, nullptr, nullptr, nullptr,
                                            Dq, Dq, Dq);
    // 7) LN2 -> xn2 planes
    ln_kernel<<<ROWS, 128>>>(x1, n2w, n2b, xn2h, xn2l);
    // 8) FFN1 + GELU -> h1 planes
    pg<4><<<dim3(16, 32, 1), 256, PG_SMEM>>>(xn2h, xn2l, w3h, w3l, l1b, nullptr,
                                             nullptr, h1h, h1l, nullptr, nullptr,
                                             Dq, Dq, Dq);
    // 9) FFN2 + residual -> final x output
    pg<5><<<dim3(4, 32, 1), 256, PG_SMEM>>>(h1h, h1l, w4h, w4l, l2b, x1,
                                            out_x, nullptr, nullptr, nullptr, nullptr,
                                            DFFq, DFFq, DFFq);
}

// round 10
// speedup vs baseline: 3.3792x; 1.6963x over previous
#include <cuda_runtime.h>
#include <cuda_fp16.h>
#include <math.h>
#include <stdint.h>

// ---------------- problem dims (fixed) ----------------
#define Lq   1024
#define Bq   4
#define Dq   512
#define Hq   8
#define DHq  64
#define DFFq 2048
#define ROWS 4096
#define BHq  32
#define QKV_ONE (BHq * Lq * DHq)   // 2097152
#define SROW 40                    // smem row stride in halves (conflict-free)

// ---------------- persistent scratch: single fp16 planes + fp32 spine ----------------
__device__ __half g_xn [ROWS * Dq];
__device__ __half g_xn2[ROWS * Dq];
__device__ __half g_q[QKV_ONE], g_k[QKV_ONE], g_v[QKV_ONE];
__device__ __half g_at[ROWS * Dq];
__device__ float  g_x1[ROWS * Dq];
__device__ __half g_h1[ROWS * DFFq];
__device__ __half g_w1[1536 * 512];   // in_proj_w
__device__ __half g_w2[512 * 512];    // out_proj_w
__device__ __half g_w3[2048 * 512];   // lin1_w
__device__ __half g_w4[512 * 2048];   // lin2_w
__device__ float g_rmax[BHq * Lq], g_rinv[BHq * Lq];

// ---------------- helpers ----------------
__device__ __forceinline__ uint32_t smem_u32(const void* p) {
    uint32_t a;
    asm("{ .reg .u64 t; cvta.to.shared.u64 t, %1; cvt.u32.u64 %0, t; }" : "=r"(a) : "l"(p));
    return a;
}
__device__ __forceinline__ void cpa16(uint32_t s, const void* g) {
    asm volatile("cp.async.cg.shared.global [%0], [%1], 16;" :: "r"(s), "l"(g) : "memory");
}
__device__ __forceinline__ void mma_f16(float* d, const uint32_t* a, const uint32_t* b) {
    asm volatile(
        "mma.sync.aligned.m16n8k16.row.col.f32.f16.f16.f32 "
        "{%0,%1,%2,%3}, {%4,%5,%6,%7}, {%8,%9}, {%0,%1,%2,%3};\n"
        : "+f"(d[0]), "+f"(d[1]), "+f"(d[2]), "+f"(d[3])
        : "r"(a[0]), "r"(a[1]), "r"(a[2]), "r"(a[3]), "r"(b[0]), "r"(b[1]));
}
__device__ __forceinline__ uint32_t pack_h2(float a, float b) {
    __half2 h = __floats2half2_rn(a, b);
    return *reinterpret_cast<uint32_t*>(&h);
}

// ---------------- fp32 -> fp16 plane converter (weights) ----------------
__global__ void __launch_bounds__(256) to_half(
    const float* __restrict__ s, __half* __restrict__ h, int n4)
{
    const int i = blockIdx.x * 256 + threadIdx.x;
    if (i >= n4) return;
    const float4 v = ((const float4*)s)[i];
    uint2 o;
    o.x = pack_h2(v.x, v.y);
    o.y = pack_h2(v.z, v.w);
    ((uint2*)h)[i] = o;
}

// ---------------- fp16 GEMM: C[M,N] = A[M,K] @ B[N,K]^T, single-pass ----------------
// block 128x128, K-chunk 32, 8 warps (4m x 2n), warp tile 32x64, cp.async 2-stage.
// MODE 0: QKV (+bias; q,k,v -> fp16 planes, scattered)
// MODE 1: QK^T (z=head; acc*0.125 + edge -> edge_out fp32)
// MODE 3: out-proj (+bias, +residual -> fp32)
// MODE 4: FFN1 (+bias, GELU -> fp16 plane)
// MODE 5: FFN2 (+bias, +residual -> fp32)
template<int MODE>
__global__ void __launch_bounds__(256, 2) pg(
    const __half* __restrict__ A, const __half* __restrict__ Bm,
    const float* __restrict__ bias, const float* __restrict__ extra,
    float* __restrict__ Cf,
    __half* __restrict__ H0, __half* __restrict__ H1, __half* __restrict__ H2,
    int K, int astr, int bstr)
{
    extern __shared__ __half sm[];
    constexpr int PL  = 128 * SROW;     // halves per plane per stage
    constexpr int STG = 2 * PL;         // A, B

    const int t = threadIdx.x, lane = t & 31, w = t >> 5;
    const int g = lane >> 2, tg = lane & 3;
    const int warp_m = (w >> 1) * 32, warp_n = (w & 1) * 64;
    const int row0 = blockIdx.y * 128, col0 = blockIdx.x * 128, z = blockIdx.z;

    const __half* pA = A;
    const __half* pB = Bm;
    if (MODE == 1) {
        const size_t off = (size_t)z * Lq * DHq;
        pA += off; pB += off;
    }

    const int lrow = t >> 1, lseg = (t & 1) * 16;   // halves
    const uint32_t sbase = smem_u32(sm);
    const uint32_t srow  = sbase + (uint32_t)(lrow * SROW + lseg) * 2;
    const int niter = K >> 5;

    auto issue = [&](int it) {
        if (it < niter) {
            const int k0 = it * 32;
            const size_t ao = (size_t)(row0 + lrow) * astr + k0 + lseg;
            const size_t bo = (size_t)(col0 + lrow) * bstr + k0 + lseg;
            uint32_t d = srow + (uint32_t)((it & 1) * STG) * 2;
            cpa16(d, pA + ao);       cpa16(d + 16, pA + ao + 8);
            d += PL * 2;
            cpa16(d, pB + bo);       cpa16(d + 16, pB + bo + 8);
            asm volatile("cp.async.commit_group;" ::: "memory");
        }
    };

    float c[2][8][4];
    #pragma unroll
    for (int i = 0; i < 2; i++)
        #pragma unroll
        for (int j = 0; j < 8; j++)
            #pragma unroll
            for (int q2 = 0; q2 < 4; q2++) c[i][j][q2] = 0.f;

    issue(0); issue(1);

    for (int it = 0; it < niter; it++) {
        if (it + 2 <= niter) asm volatile("cp.async.wait_group 1;" ::: "memory");
        else                 asm volatile("cp.async.wait_group 0;" ::: "memory");
        __syncthreads();

        const __half* AS = sm + (it & 1) * STG;
        const __half* BS = AS + PL;

        #pragma unroll
        for (int kk = 0; kk < 32; kk += 16) {
            uint32_t ah[2][4];
            #pragma unroll
            for (int mi = 0; mi < 2; mi++) {
                const int rb = (warp_m + mi * 16 + g) * SROW + kk + tg * 2;
                ah[mi][0] = *(const uint32_t*)(AS + rb);
                ah[mi][1] = *(const uint32_t*)(AS + rb + 8 * SROW);
                ah[mi][2] = *(const uint32_t*)(AS + rb + 8);
                ah[mi][3] = *(const uint32_t*)(AS + rb + 8 * SROW + 8);
            }
            #pragma unroll
            for (int ni = 0; ni < 8; ni++) {
                const int nb = (warp_n + ni * 8 + g) * SROW + kk + tg * 2;
                uint32_t bh[2];
                bh[0] = *(const uint32_t*)(BS + nb);
                bh[1] = *(const uint32_t*)(BS + nb + 8);
                mma_f16(c[0][ni], ah[0], bh);
                mma_f16(c[1][ni], ah[1], bh);
            }
        }
        __syncthreads();
        issue(it + 2);
    }

    // ---------------- epilogue ----------------
    #pragma unroll
    for (int mi = 0; mi < 2; mi++)
    #pragma unroll
    for (int ni = 0; ni < 8; ni++) {
        const int cg = col0 + warp_n + ni * 8 + tg * 2;
        #pragma unroll
        for (int hf = 0; hf < 2; hf++) {
            const int r = row0 + warp_m + mi * 16 + g + hf * 8;
            float v0 = c[mi][ni][hf * 2 + 0];
            float v1 = c[mi][ni][hf * 2 + 1];

            if (MODE == 1) {
                const size_t off = (size_t)z * (Lq * Lq) + (size_t)r * Lq + cg;
                const float2 e = *(const float2*)(extra + off);
                *(float2*)(Cf + off) = make_float2(v0 * 0.125f + e.x, v1 * 0.125f + e.y);
            } else if (MODE == 0) {
                const float2 bb = *(const float2*)(bias + cg);
                v0 += bb.x; v1 += bb.y;
                const int which = cg >> 9, cc = cg & 511, h = cc >> 6, dh0 = cc & 63;
                const int l = r >> 2, b = r & 3;
                const size_t o = ((size_t)(b * Hq + h) * Lq + l) * DHq + dh0;
                const uint32_t p = pack_h2(v0, v1);
                __half* dst = (which == 0) ? H0 : ((which == 1) ? H1 : H2);
                *(uint32_t*)(dst + o) = p;
            } else if (MODE == 4) {
                const float2 bb = *(const float2*)(bias + cg);
                v0 += bb.x; v1 += bb.y;
                v0 = 0.5f * v0 * (1.f + erff(v0 * 0.70710678118654752f));
                v1 = 0.5f * v1 * (1.f + erff(v1 * 0.70710678118654752f));
                *(uint32_t*)(H0 + (size_t)r * DFFq + cg) = pack_h2(v0, v1);
            } else {   // MODE 3 / 5: bias + residual -> fp32
                const float2 bb = *(const float2*)(bias + cg);
                const size_t o = (size_t)r * Dq + cg;
                const float2 e = *(const float2*)(extra + o);
                *(float2*)(Cf + o) = make_float2(v0 + bb.x + e.x, v1 + bb.y + e.y);
            }
        }
    }
}

// ---------------- PV GEMM (softmax on the fly) -> attn fp16 plane ----------
__global__ void __launch_bounds__(256) pv_gemm(
    const float* __restrict__ S, const __half* __restrict__ V,
    const float* __restrict__ rmax, const float* __restrict__ rinv,
    __half* __restrict__ O)
{
    extern __shared__ __half sm[];
    constexpr int A_SZ = 128 * SROW;
    constexpr int B_SZ = 64 * SROW;
    constexpr int STG  = A_SZ + B_SZ;

    const int t = threadIdx.x, lane = t & 31, w = t >> 5;
    const int g = lane >> 2, tg = lane & 3;
    const int warp_m = (w >> 1) * 32, warp_n = (w & 1) * 32;
    const int row0 = blockIdx.y * 128, z = blockIdx.z;

    const float* Ap = S + (size_t)z * (Lq * Lq);
    const __half* Bp = V + (size_t)z * (Lq * DHq);

    const int arow = t >> 1, aseg = t & 1;
    const int vk = t >> 3, vn0 = (t & 7) * 8;

    const int grow = z * Lq + row0 + arow;
    const float mx = rmax[grow], iv = rinv[grow];

    float4 av[4];
    uint4 bv;
    const int niter = Lq >> 5;   // 32

    auto g_load = [&](int it) {
        const int k0 = it * 32;
        const float* ap = Ap + (size_t)(row0 + arow) * Lq + k0 + aseg * 16;
        #pragma unroll
        for (int i = 0; i < 4; i++) {
            av[i] = *(const float4*)(ap + i * 4);
            av[i].x = expf(av[i].x - mx) * iv;
            av[i].y = expf(av[i].y - mx) * iv;
            av[i].z = expf(av[i].z - mx) * iv;
            av[i].w = expf(av[i].w - mx) * iv;
        }
        bv = *(const uint4*)(Bp + (size_t)(k0 + vk) * DHq + vn0);
    };

    auto s_store = [&](int s) {
        __half* AS = sm + s * STG;
        __half* BS = AS + A_SZ;
        {
            uint32_t hw[8];
            #pragma unroll
            for (int i = 0; i < 4; i++) {
                hw[2*i]   = pack_h2(av[i].x, av[i].y);
                hw[2*i+1] = pack_h2(av[i].z, av[i].w);
            }
            const int off = arow * SROW + aseg * 16;
            *(uint4*)(AS + off)     = make_uint4(hw[0], hw[1], hw[2], hw[3]);
            *(uint4*)(AS + off + 8) = make_uint4(hw[4], hw[5], hw[6], hw[7]);
        }
        {
            const __half* hv = (const __half*)&bv;
            #pragma unroll
            for (int j = 0; j < 8; j++)
                BS[(vn0 + j) * SROW + vk] = hv[j];
        }
    };

    float c[2][4][4];
    #pragma unroll
    for (int mi = 0; mi < 2; mi++)
        #pragma unroll
        for (int ni = 0; ni < 4; ni++)
            #pragma unroll
            for (int j = 0; j < 4; j++) c[mi][ni][j] = 0.f;

    g_load(0); s_store(0); __syncthreads();

    for (int it = 0; it < niter; it++) {
        if (it + 1 < niter) g_load(it + 1);
        const int s = it & 1;
        const __half* AS = sm + s * STG;
        const __half* BS = AS + A_SZ;

        #pragma unroll
        for (int kk = 0; kk < 32; kk += 16) {
            uint32_t ah[2][4], bh[4][2];
            #pragma unroll
            for (int mi = 0; mi < 2; mi++) {
                const int rb = (warp_m + mi * 16 + g) * SROW + kk + tg * 2;
                ah[mi][0] = *(const uint32_t*)(AS + rb);
                ah[mi][1] = *(const uint32_t*)(AS + rb + 8 * SROW);
                ah[mi][2] = *(const uint32_t*)(AS + rb + 8);
                ah[mi][3] = *(const uint32_t*)(AS + rb + 8 * SROW + 8);
            }
            #pragma unroll
            for (int ni = 0; ni < 4; ni++) {
                const int nb = (warp_n + ni * 8 + g) * SROW + kk + tg * 2;
                bh[ni][0] = *(const uint32_t*)(BS + nb);
                bh[ni][1] = *(const uint32_t*)(BS + nb + 8);
            }
            #pragma unroll
            for (int mi = 0; mi < 2; mi++)
                #pragma unroll
                for (int ni = 0; ni < 4; ni++)
                    mma_f16(c[mi][ni], ah[mi], bh[ni]);
        }
        if (it + 1 < niter) s_store((it + 1) & 1);
        __syncthreads();
    }

    // epilogue -> attn fp16 plane, layout [l][b][h*64+dh]
    const int b = z >> 3, h = z & 7;
    #pragma unroll
    for (int mi = 0; mi < 2; mi++)
    #pragma unroll
    for (int ni = 0; ni < 4; ni++) {
        const int cg = warp_n + ni * 8 + tg * 2;
        #pragma unroll
        for (int hf = 0; hf < 2; hf++) {
            const int r = row0 + warp_m + mi * 16 + g + hf * 8;
            const size_t o = ((size_t)r * Bq + b) * Dq + h * DHq + cg;
            *(uint32_t*)(O + o) = pack_h2(c[mi][ni][hf * 2 + 0], c[mi][ni][hf * 2 + 1]);
        }
    }
}

// ---------------- LayerNorm -> fp16 plane ----------------
__global__ void __launch_bounds__(128) ln_kernel(
    const float* __restrict__ x, const float* __restrict__ w,
    const float* __restrict__ b, __half* __restrict__ y)
{
    const int row = blockIdx.x;
    const int t = threadIdx.x;
    const float4 v = ((const float4*)(x + (size_t)row * Dq))[t];
    float s  = v.x + v.y + v.z + v.w;
    float ss = v.x*v.x + v.y*v.y + v.z*v.z + v.w*v.w;
#pragma unroll
    for (int o = 16; o > 0; o >>= 1) {
        s  += __shfl_xor_sync(0xffffffffu, s,  o);
        ss += __shfl_xor_sync(0xffffffffu, ss, o);
    }
    __shared__ float sh[8];
    const int wi = t >> 5, lane = t & 31;
    if (lane == 0) { sh[wi] = s; sh[4 + wi] = ss; }
    __syncthreads();
    s  = sh[0] + sh[1] + sh[2] + sh[3];
    ss = sh[4] + sh[5] + sh[6] + sh[7];
    const float mu  = s * (1.f / Dq);
    const float var = ss * (1.f / Dq) - mu * mu;
    const float rs  = rsqrtf(var + 1e-5f);
    const float4 wv = ((const float4*)w)[t];
    const float4 bv = ((const float4*)b)[t];
    const float o0 = (v.x - mu) * rs * wv.x + bv.x;
    const float o1 = (v.y - mu) * rs * wv.y + bv.y;
    const float o2 = (v.z - mu) * rs * wv.z + bv.z;
    const float o3 = (v.w - mu) * rs * wv.w + bv.w;
    uint2 o;
    o.x = pack_h2(o0, o1);
    o.y = pack_h2(o2, o3);
    ((uint2*)(y + (size_t)row * Dq))[t] = o;
}

// ---------------- softmax row stats ----------------
__global__ void __launch_bounds__(256) row_stats(
    const float* __restrict__ s, float* __restrict__ rmax, float* __restrict__ rinv)
{
    const int row  = blockIdx.x * 8 + (threadIdx.x >> 5);
    const int lane = threadIdx.x & 31;
    const float4* sr = (const float4*)(s + (size_t)row * Lq);
    float4 v[8];
    float m = -1e30f;
#pragma unroll
    for (int i = 0; i < 8; i++) {
        v[i] = sr[lane + i * 32];
        m = fmaxf(m, fmaxf(fmaxf(v[i].x, v[i].y), fmaxf(v[i].z, v[i].w)));
    }
#pragma unroll
    for (int o = 16; o > 0; o >>= 1) m = fmaxf(m, __shfl_xor_sync(0xffffffffu, m, o));
    float sum = 0.f;
#pragma unroll
    for (int i = 0; i < 8; i++)
        sum += expf(v[i].x - m) + expf(v[i].y - m) + expf(v[i].z - m) + expf(v[i].w - m);
#pragma unroll
    for (int o = 16; o > 0; o >>= 1) sum += __shfl_xor_sync(0xffffffffu, sum, o);
    if (lane == 0) { rmax[row] = m; rinv[row] = 1.f / sum; }
}

// ---------------- launch ----------------
extern "C" void kernel_launch(void* const* d_in, const int* in_sizes, int n_in,
                              void* d_out, int out_size)
{
    (void)in_sizes; (void)n_in; (void)out_size;
    const float* x    = (const float*)d_in[0];
    const float* edge = (const float*)d_in[1];
    const float* inw  = (const float*)d_in[2];
    const float* inb  = (const float*)d_in[3];
    const float* outw = (const float*)d_in[4];
    const float* outb = (const float*)d_in[5];
    const float* l1w  = (const float*)d_in[6];
    const float* l1b  = (const float*)d_in[7];
    const float* l2w  = (const float*)d_in[8];
    const float* l2b  = (const float*)d_in[9];
    const float* n1w  = (const float*)d_in[10];
    const float* n1b  = (const float*)d_in[11];
    const float* n2w  = (const float*)d_in[12];
    const float* n2b  = (const float*)d_in[13];

    __half *xn,*xn2,*q,*k,*v,*at,*h1,*w1,*w2,*w3,*w4;
    float *x1, *rmax, *rinv;
    cudaGetSymbolAddress((void**)&xn,   g_xn);
    cudaGetSymbolAddress((void**)&xn2,  g_xn2);
    cudaGetSymbolAddress((void**)&q,    g_q);
    cudaGetSymbolAddress((void**)&k,    g_k);
    cudaGetSymbolAddress((void**)&v,    g_v);
    cudaGetSymbolAddress((void**)&at,   g_at);
    cudaGetSymbolAddress((void**)&h1,   g_h1);
    cudaGetSymbolAddress((void**)&w1,   g_w1);
    cudaGetSymbolAddress((void**)&w2,   g_w2);
    cudaGetSymbolAddress((void**)&w3,   g_w3);
    cudaGetSymbolAddress((void**)&w4,   g_w4);
    cudaGetSymbolAddress((void**)&x1,   g_x1);
    cudaGetSymbolAddress((void**)&rmax, g_rmax);
    cudaGetSymbolAddress((void**)&rinv, g_rinv);

    float* out_x    = (float*)d_out;
    float* edge_out = out_x + (size_t)ROWS * Dq;

    const int PG_SMEM = 2 * 2 * 128 * SROW * (int)sizeof(__half);               // 40960
    const int PV_SMEM = 2 * (128 * SROW + 64 * SROW) * (int)sizeof(__half);     // 30720
    cudaFuncSetAttribute(pg<0>, cudaFuncAttributeMaxDynamicSharedMemorySize, PG_SMEM);
    cudaFuncSetAttribute(pg<1>, cudaFuncAttributeMaxDynamicSharedMemorySize, PG_SMEM);
    cudaFuncSetAttribute(pg<3>, cudaFuncAttributeMaxDynamicSharedMemorySize, PG_SMEM);
    cudaFuncSetAttribute(pg<4>, cudaFuncAttributeMaxDynamicSharedMemorySize, PG_SMEM);
    cudaFuncSetAttribute(pg<5>, cudaFuncAttributeMaxDynamicSharedMemorySize, PG_SMEM);
    cudaFuncSetAttribute(pv_gemm, cudaFuncAttributeMaxDynamicSharedMemorySize, PV_SMEM);

    // 0) weights -> fp16 planes
    to_half<<<768, 256>>>(inw,  w1, 1536 * 512 / 4);
    to_half<<<256, 256>>>(outw, w2, 512 * 512 / 4);
    to_half<<<1024, 256>>>(l1w, w3, 2048 * 512 / 4);
    to_half<<<1024, 256>>>(l2w, w4, 512 * 2048 / 4);
    // 1) LN1 -> xn plane
    ln_kernel<<<ROWS, 128>>>(x, n1w, n1b, xn);
    // 2) QKV: q,k,v -> fp16 planes (scattered)
    pg<0><<<dim3(12, 32, 1), 256, PG_SMEM>>>(xn, w1, inb, nullptr,
                                             nullptr, q, k, v, Dq, Dq, Dq);
    // 3) scores: t = (q@k^T)/8 + edge -> edge_out
    pg<1><<<dim3(8, 8, BHq), 256, PG_SMEM>>>(q, k, nullptr, edge,
                                             edge_out, nullptr, nullptr, nullptr,
                                             DHq, DHq, DHq);
    // 4) softmax row stats
    row_stats<<<(BHq * Lq) / 8, 256>>>(edge_out, rmax, rinv);
    // 5) attn @ V -> attn plane
    pv_gemm<<<dim3(1, 8, BHq), 256, PV_SMEM>>>(edge_out, v, rmax, rinv, at);
    // 6) out projection + residual -> x1 fp32
    pg<3><<<dim3(4, 32, 1), 256, PG_SMEM>>>(at, w2, outb, x,
                                            x1, nullptr, nullptr, nullptr,
                                            Dq, Dq, Dq);
    // 7) LN2 -> xn2 plane
    ln_kernel<<<ROWS, 128>>>(x1, n2w, n2b, xn2);
    // 8) FFN1 + GELU -> h1 plane
    pg<4><<<dim3(16, 32, 1), 256, PG_SMEM>>>(xn2, w3, l1b, nullptr,
                                             nullptr, h1, nullptr, nullptr,
                                             Dq, Dq, Dq);
    // 9) FFN2 + residual -> final x output
    pg<5><<<dim3(4, 32, 1), 256, PG_SMEM>>>(h1, w4, l2b, x1,
                                            out_x, nullptr, nullptr, nullptr,
                                            DFFq, DFFq, DFFq);
}

// round 11
// speedup vs baseline: 3.9190x; 1.1598x over previous
#include <cuda_runtime.h>
#include <cuda_fp16.h>
#include <math.h>
#include <stdint.h>

// ---------------- problem dims (fixed) ----------------
#define Lq   1024
#define Bq   4
#define Dq   512
#define Hq   8
#define DHq  64
#define DFFq 2048
#define ROWS 4096
#define BHq  32
#define QKV_ONE (BHq * Lq * DHq)   // 2097152
#define SROW 40                    // pg smem row stride in halves
#define QROW 72                    // flash Q/K smem stride (64+8)
#define VROW 136                   // flash V smem stride (128+8)

// ---------------- persistent scratch ----------------
__device__ __half g_xn [ROWS * Dq];
__device__ __half g_xn2[ROWS * Dq];
__device__ __half g_q[QKV_ONE], g_k[QKV_ONE];
__device__ __half g_vT[QKV_ONE];            // [bh][dh][l]  (pre-transposed)
__device__ __half g_at[ROWS * Dq];
__device__ float  g_x1[ROWS * Dq];
__device__ __half g_h1[ROWS * DFFq];
__device__ __half g_w1[1536 * 512];
__device__ __half g_w2[512 * 512];
__device__ __half g_w3[2048 * 512];
__device__ __half g_w4[512 * 2048];

// ---------------- helpers ----------------
__device__ __forceinline__ uint32_t smem_u32(const void* p) {
    uint32_t a;
    asm("{ .reg .u64 t; cvta.to.shared.u64 t, %1; cvt.u32.u64 %0, t; }" : "=r"(a) : "l"(p));
    return a;
}
__device__ __forceinline__ void cpa16(uint32_t s, const void* g) {
    asm volatile("cp.async.cg.shared.global [%0], [%1], 16;" :: "r"(s), "l"(g) : "memory");
}
__device__ __forceinline__ void mma_f16(float* d, const uint32_t* a, const uint32_t* b) {
    asm volatile(
        "mma.sync.aligned.m16n8k16.row.col.f32.f16.f16.f32 "
        "{%0,%1,%2,%3}, {%4,%5,%6,%7}, {%8,%9}, {%0,%1,%2,%3};\n"
        : "+f"(d[0]), "+f"(d[1]), "+f"(d[2]), "+f"(d[3])
        : "r"(a[0]), "r"(a[1]), "r"(a[2]), "r"(a[3]), "r"(b[0]), "r"(b[1]));
}
__device__ __forceinline__ uint32_t pack_h2(float a, float b) {
    __half2 h = __floats2half2_rn(a, b);
    return *reinterpret_cast<uint32_t*>(&h);
}

// ---------------- fp32 -> fp16 converter (weights) ----------------
__global__ void __launch_bounds__(256) to_half(
    const float* __restrict__ s, __half* __restrict__ h, int n4)
{
    const int i = blockIdx.x * 256 + threadIdx.x;
    if (i >= n4) return;
    const float4 v = ((const float4*)s)[i];
    uint2 o;
    o.x = pack_h2(v.x, v.y);
    o.y = pack_h2(v.z, v.w);
    ((uint2*)h)[i] = o;
}

// ---------------- fp16 GEMM: C = A @ B^T (projections / FFN) ----------------
// MODE 0: QKV (+bias; q,k planes; v pre-transposed)
// MODE 3: out-proj (+bias, +residual -> fp32)
// MODE 4: FFN1 (+bias, GELU -> fp16 plane)
// MODE 5: FFN2 (+bias, +residual -> fp32)
template<int MODE>
__global__ void __launch_bounds__(256, 2) pg(
    const __half* __restrict__ A, const __half* __restrict__ Bm,
    const float* __restrict__ bias, const float* __restrict__ extra,
    float* __restrict__ Cf,
    __half* __restrict__ H0, __half* __restrict__ H1, __half* __restrict__ H2,
    int K, int astr, int bstr)
{
    extern __shared__ __half sm[];
    constexpr int PL  = 128 * SROW;
    constexpr int STG = 2 * PL;

    const int t = threadIdx.x, lane = t & 31, w = t >> 5;
    const int g = lane >> 2, tg = lane & 3;
    const int warp_m = (w >> 1) * 32, warp_n = (w & 1) * 64;
    const int row0 = blockIdx.y * 128, col0 = blockIdx.x * 128;

    const int lrow = t >> 1, lseg = (t & 1) * 16;
    const uint32_t sbase = smem_u32(sm);
    const uint32_t srow  = sbase + (uint32_t)(lrow * SROW + lseg) * 2;
    const int niter = K >> 5;

    auto issue = [&](int it) {
        if (it < niter) {
            const int k0 = it * 32;
            const size_t ao = (size_t)(row0 + lrow) * astr + k0 + lseg;
            const size_t bo = (size_t)(col0 + lrow) * bstr + k0 + lseg;
            uint32_t d = srow + (uint32_t)((it & 1) * STG) * 2;
            cpa16(d, A + ao);        cpa16(d + 16, A + ao + 8);
            d += PL * 2;
            cpa16(d, Bm + bo);       cpa16(d + 16, Bm + bo + 8);
            asm volatile("cp.async.commit_group;" ::: "memory");
        }
    };

    float c[2][8][4];
    #pragma unroll
    for (int i = 0; i < 2; i++)
        #pragma unroll
        for (int j = 0; j < 8; j++)
            #pragma unroll
            for (int q2 = 0; q2 < 4; q2++) c[i][j][q2] = 0.f;

    issue(0); issue(1);

    for (int it = 0; it < niter; it++) {
        if (it + 2 <= niter) asm volatile("cp.async.wait_group 1;" ::: "memory");
        else                 asm volatile("cp.async.wait_group 0;" ::: "memory");
        __syncthreads();

        const __half* AS = sm + (it & 1) * STG;
        const __half* BS = AS + PL;

        #pragma unroll
        for (int kk = 0; kk < 32; kk += 16) {
            uint32_t ah[2][4];
            #pragma unroll
            for (int mi = 0; mi < 2; mi++) {
                const int rb = (warp_m + mi * 16 + g) * SROW + kk + tg * 2;
                ah[mi][0] = *(const uint32_t*)(AS + rb);
                ah[mi][1] = *(const uint32_t*)(AS + rb + 8 * SROW);
                ah[mi][2] = *(const uint32_t*)(AS + rb + 8);
                ah[mi][3] = *(const uint32_t*)(AS + rb + 8 * SROW + 8);
            }
            #pragma unroll
            for (int ni = 0; ni < 8; ni++) {
                const int nb = (warp_n + ni * 8 + g) * SROW + kk + tg * 2;
                uint32_t bh[2];
                bh[0] = *(const uint32_t*)(BS + nb);
                bh[1] = *(const uint32_t*)(BS + nb + 8);
                mma_f16(c[0][ni], ah[0], bh);
                mma_f16(c[1][ni], ah[1], bh);
            }
        }
        __syncthreads();
        issue(it + 2);
    }

    #pragma unroll
    for (int mi = 0; mi < 2; mi++)
    #pragma unroll
    for (int ni = 0; ni < 8; ni++) {
        const int cg = col0 + warp_n + ni * 8 + tg * 2;
        #pragma unroll
        for (int hf = 0; hf < 2; hf++) {
            const int r = row0 + warp_m + mi * 16 + g + hf * 8;
            float v0 = c[mi][ni][hf * 2 + 0];
            float v1 = c[mi][ni][hf * 2 + 1];

            if (MODE == 0) {
                const float2 bb = *(const float2*)(bias + cg);
                v0 += bb.x; v1 += bb.y;
                const int which = cg >> 9, cc = cg & 511, h = cc >> 6, dh0 = cc & 63;
                const int l = r >> 2, b = r & 3;
                const int bh = b * Hq + h;
                if (which == 2) {
                    // V pre-transposed: [bh][dh][l]
                    H2[((size_t)bh * DHq + dh0)     * Lq + l] = __float2half_rn(v0);
                    H2[((size_t)bh * DHq + dh0 + 1) * Lq + l] = __float2half_rn(v1);
                } else {
                    const size_t o = ((size_t)bh * Lq + l) * DHq + dh0;
                    __half* dst = (which == 0) ? H0 : H1;
                    *(uint32_t*)(dst + o) = pack_h2(v0, v1);
                }
            } else if (MODE == 4) {
                const float2 bb = *(const float2*)(bias + cg);
                v0 += bb.x; v1 += bb.y;
                v0 = 0.5f * v0 * (1.f + erff(v0 * 0.70710678118654752f));
                v1 = 0.5f * v1 * (1.f + erff(v1 * 0.70710678118654752f));
                *(uint32_t*)(H0 + (size_t)r * DFFq + cg) = pack_h2(v0, v1);
            } else {   // MODE 3 / 5
                const float2 bb = *(const float2*)(bias + cg);
                const size_t o = (size_t)r * Dq + cg;
                const float2 e = *(const float2*)(extra + o);
                *(float2*)(Cf + o) = make_float2(v0 + bb.x + e.x, v1 + bb.y + e.y);
            }
        }
    }
}

// ---------------- flash attention: S=QK^T/8+edge -> edge_out; O=softmax(S)@V ----
// grid (8 row-blocks, 32 heads), 256 threads = 8 warps, warp owns 16 rows fully.
__global__ void __launch_bounds__(256) flash(
    const __half* __restrict__ Q, const __half* __restrict__ Kg,
    const __half* __restrict__ VT,
    const float* __restrict__ edge, float* __restrict__ edge_out,
    __half* __restrict__ O)
{
    extern __shared__ __half sm[];
    __half* Qs = sm;                         // 128 x QROW
    __half* Ks = Qs + 128 * QROW;            // 2 stages x 128 x QROW
    __half* Vs = Ks + 2 * 128 * QROW;        // 2 stages x 64 x VROW

    const int t = threadIdx.x, lane = t & 31, w = t >> 5;
    const int g = lane >> 2, tg = lane & 3;
    const int z = blockIdx.y, row0 = blockIdx.x * 128;
    const int bb_ = z >> 3, hh_ = z & 7;

    const __half* Qp = Q  + (size_t)z * Lq * DHq;
    const __half* Kp = Kg + (size_t)z * Lq * DHq;
    const __half* Vp = VT + (size_t)z * DHq * Lq;

    const uint32_t qs_u = smem_u32(Qs);
    const uint32_t ks_u = smem_u32(Ks);
    const uint32_t vs_u = smem_u32(Vs);

    // loader mappings
    const int qrow = t >> 1, qcol = (t & 1) * 32;      // Q/K: 128 rows x 64 halves
    const int vrow = t >> 2, vcol = (t & 3) * 32;      // V: 64 rows x 128 halves

    auto issue = [&](int ct, bool withQ) {
        if (ct < 8) {
            const int s = ct & 1;
            const int c0 = ct * 128;
            if (withQ) {
                #pragma unroll
                for (int j = 0; j < 4; j++)
                    cpa16(qs_u + (uint32_t)(qrow * QROW + qcol + j * 8) * 2,
                          Qp + (size_t)(row0 + qrow) * DHq + qcol + j * 8);
            }
            #pragma unroll
            for (int j = 0; j < 4; j++)
                cpa16(ks_u + (uint32_t)(s * 128 * QROW + qrow * QROW + qcol + j * 8) * 2,
                      Kp + (size_t)(c0 + qrow) * DHq + qcol + j * 8);
            #pragma unroll
            for (int j = 0; j < 4; j++)
                cpa16(vs_u + (uint32_t)(s * 64 * VROW + vrow * VROW + vcol + j * 8) * 2,
                      Vp + (size_t)vrow * Lq + c0 + vcol + j * 8);
            asm volatile("cp.async.commit_group;" ::: "memory");
        }
    };

    issue(0, true); issue(1, false);

    uint32_t qa[4][4];
    float oc[8][4];
    #pragma unroll
    for (int dt = 0; dt < 8; dt++)
        #pragma unroll
        for (int j = 0; j < 4; j++) oc[dt][j] = 0.f;
    float m0 = -1e30f, m1 = -1e30f, l0 = 0.f, l1 = 0.f;

    const int r0 = row0 + w * 16 + g;
    const int r1 = r0 + 8;

    for (int ct = 0; ct < 8; ct++) {
        if (ct + 2 <= 8) asm volatile("cp.async.wait_group 1;" ::: "memory");
        else             asm volatile("cp.async.wait_group 0;" ::: "memory");
        __syncthreads();

        if (ct == 0) {
            #pragma unroll
            for (int ki = 0; ki < 4; ki++) {
                const int rb = (w * 16 + g) * QROW + ki * 16 + tg * 2;
                qa[ki][0] = *(const uint32_t*)(Qs + rb);
                qa[ki][1] = *(const uint32_t*)(Qs + rb + 8 * QROW);
                qa[ki][2] = *(const uint32_t*)(Qs + rb + 8);
                qa[ki][3] = *(const uint32_t*)(Qs + rb + 8 * QROW + 8);
            }
        }

        const __half* KS = Ks + (ct & 1) * 128 * QROW;
        const __half* VS = Vs + (ct & 1) * 64 * VROW;
        const int c0 = ct * 128;

        #pragma unroll
        for (int sub = 0; sub < 2; sub++) {
            // ---- S = Q @ K^T over this 64-col sub-tile ----
            float sf[8][4];
            #pragma unroll
            for (int nt = 0; nt < 8; nt++) {
                sf[nt][0] = sf[nt][1] = sf[nt][2] = sf[nt][3] = 0.f;
                const int nrow = (sub * 64 + nt * 8 + g) * QROW + tg * 2;
                #pragma unroll
                for (int ki = 0; ki < 4; ki++) {
                    uint32_t bh2[2];
                    bh2[0] = *(const uint32_t*)(KS + nrow + ki * 16);
                    bh2[1] = *(const uint32_t*)(KS + nrow + ki * 16 + 8);
                    mma_f16(sf[nt], qa[ki], bh2);
                }
            }
            // ---- scale + edge; write edge_out ----
            #pragma unroll
            for (int nt = 0; nt < 8; nt++) {
                const int col = c0 + sub * 64 + nt * 8 + tg * 2;
                const size_t e0 = ((size_t)z * Lq + r0) * Lq + col;
                const size_t e1 = ((size_t)z * Lq + r1) * Lq + col;
                const float2 ea = *(const float2*)(edge + e0);
                const float2 eb = *(const float2*)(edge + e1);
                sf[nt][0] = sf[nt][0] * 0.125f + ea.x;
                sf[nt][1] = sf[nt][1] * 0.125f + ea.y;
                sf[nt][2] = sf[nt][2] * 0.125f + eb.x;
                sf[nt][3] = sf[nt][3] * 0.125f + eb.y;
                *(float2*)(edge_out + e0) = make_float2(sf[nt][0], sf[nt][1]);
                *(float2*)(edge_out + e1) = make_float2(sf[nt][2], sf[nt][3]);
            }
            // ---- online softmax ----
            float tm0 = -1e30f, tm1 = -1e30f;
            #pragma unroll
            for (int nt = 0; nt < 8; nt++) {
                tm0 = fmaxf(tm0, fmaxf(sf[nt][0], sf[nt][1]));
                tm1 = fmaxf(tm1, fmaxf(sf[nt][2], sf[nt][3]));
            }
            tm0 = fmaxf(tm0, __shfl_xor_sync(0xffffffffu, tm0, 1));
            tm0 = fmaxf(tm0, __shfl_xor_sync(0xffffffffu, tm0, 2));
            tm1 = fmaxf(tm1, __shfl_xor_sync(0xffffffffu, tm1, 1));
            tm1 = fmaxf(tm1, __shfl_xor_sync(0xffffffffu, tm1, 2));
            const float m0n = fmaxf(m0, tm0), m1n = fmaxf(m1, tm1);
            const float a0 = expf(m0 - m0n), a1 = expf(m1 - m1n);
            m0 = m0n; m1 = m1n;
            float rs0 = 0.f, rs1 = 0.f;
            #pragma unroll
            for (int nt = 0; nt < 8; nt++) {
                sf[nt][0] = expf(sf[nt][0] - m0n);
                sf[nt][1] = expf(sf[nt][1] - m0n);
                sf[nt][2] = expf(sf[nt][2] - m1n);
                sf[nt][3] = expf(sf[nt][3] - m1n);
                rs0 += sf[nt][0] + sf[nt][1];
                rs1 += sf[nt][2] + sf[nt][3];
            }
            rs0 += __shfl_xor_sync(0xffffffffu, rs0, 1);
            rs0 += __shfl_xor_sync(0xffffffffu, rs0, 2);
            rs1 += __shfl_xor_sync(0xffffffffu, rs1, 1);
            rs1 += __shfl_xor_sync(0xffffffffu, rs1, 2);
            l0 = a0 * l0 + rs0;
            l1 = a1 * l1 + rs1;
            #pragma unroll
            for (int dt = 0; dt < 8; dt++) {
                oc[dt][0] *= a0; oc[dt][1] *= a0;
                oc[dt][2] *= a1; oc[dt][3] *= a1;
            }
            // ---- O += P @ V ----
            #pragma unroll
            for (int ki = 0; ki < 4; ki++) {
                uint32_t pa[4];
                pa[0] = pack_h2(sf[2*ki][0],   sf[2*ki][1]);
                pa[1] = pack_h2(sf[2*ki][2],   sf[2*ki][3]);
                pa[2] = pack_h2(sf[2*ki+1][0], sf[2*ki+1][1]);
                pa[3] = pack_h2(sf[2*ki+1][2], sf[2*ki+1][3]);
                #pragma unroll
                for (int dt = 0; dt < 8; dt++) {
                    const int nb = (dt * 8 + g) * VROW + sub * 64 + ki * 16 + tg * 2;
                    uint32_t vb[2];
                    vb[0] = *(const uint32_t*)(VS + nb);
                    vb[1] = *(const uint32_t*)(VS + nb + 8);
                    mma_f16(oc[dt], pa, vb);
                }
            }
        }
        __syncthreads();
        issue(ct + 2, false);
    }

    // ---- normalize + write attn plane [l][b][h*64+dh] ----
    const float il0 = 1.f / l0, il1 = 1.f / l1;
    #pragma unroll
    for (int dt = 0; dt < 8; dt++) {
        const int dh = hh_ * DHq + dt * 8 + tg * 2;
        *(uint32_t*)(O + ((size_t)r0 * Bq + bb_) * Dq + dh) =
            pack_h2(oc[dt][0] * il0, oc[dt][1] * il0);
        *(uint32_t*)(O + ((size_t)r1 * Bq + bb_) * Dq + dh) =
            pack_h2(oc[dt][2] * il1, oc[dt][3] * il1);
    }
}

// ---------------- LayerNorm -> fp16 plane ----------------
__global__ void __launch_bounds__(128) ln_kernel(
    const float* __restrict__ x, const float* __restrict__ w,
    const float* __restrict__ b, __half* __restrict__ y)
{
    const int row = blockIdx.x;
    const int t = threadIdx.x;
    const float4 v = ((const float4*)(x + (size_t)row * Dq))[t];
    float s  = v.x + v.y + v.z + v.w;
    float ss = v.x*v.x + v.y*v.y + v.z*v.z + v.w*v.w;
#pragma unroll
    for (int o = 16; o > 0; o >>= 1) {
        s  += __shfl_xor_sync(0xffffffffu, s,  o);
        ss += __shfl_xor_sync(0xffffffffu, ss, o);
    }
    __shared__ float sh[8];
    const int wi = t >> 5, lane = t & 31;
    if (lane == 0) { sh[wi] = s; sh[4 + wi] = ss; }
    __syncthreads();
    s  = sh[0] + sh[1] + sh[2] + sh[3];
    ss = sh[4] + sh[5] + sh[6] + sh[7];
    const float mu  = s * (1.f / Dq);
    const float var = ss * (1.f / Dq) - mu * mu;
    const float rs  = rsqrtf(var + 1e-5f);
    const float4 wv = ((const float4*)w)[t];
    const float4 bv = ((const float4*)b)[t];
    uint2 o;
    o.x = pack_h2((v.x - mu) * rs * wv.x + bv.x, (v.y - mu) * rs * wv.y + bv.y);
    o.y = pack_h2((v.z - mu) * rs * wv.z + bv.z, (v.w - mu) * rs * wv.w + bv.w);
    ((uint2*)(y + (size_t)row * Dq))[t] = o;
}

// ---------------- launch ----------------
extern "C" void kernel_launch(void* const* d_in, const int* in_sizes, int n_in,
                              void* d_out, int out_size)
{
    (void)in_sizes; (void)n_in; (void)out_size;
    const float* x    = (const float*)d_in[0];
    const float* edge = (const float*)d_in[1];
    const float* inw  = (const float*)d_in[2];
    const float* inb  = (const float*)d_in[3];
    const float* outw = (const float*)d_in[4];
    const float* outb = (const float*)d_in[5];
    const float* l1w  = (const float*)d_in[6];
    const float* l1b  = (const float*)d_in[7];
    const float* l2w  = (const float*)d_in[8];
    const float* l2b  = (const float*)d_in[9];
    const float* n1w  = (const float*)d_in[10];
    const float* n1b  = (const float*)d_in[11];
    const float* n2w  = (const float*)d_in[12];
    const float* n2b  = (const float*)d_in[13];

    __half *xn,*xn2,*q,*k,*vT,*at,*h1,*w1,*w2,*w3,*w4;
    float *x1;
    cudaGetSymbolAddress((void**)&xn,   g_xn);
    cudaGetSymbolAddress((void**)&xn2,  g_xn2);
    cudaGetSymbolAddress((void**)&q,    g_q);
    cudaGetSymbolAddress((void**)&k,    g_k);
    cudaGetSymbolAddress((void**)&vT,   g_vT);
    cudaGetSymbolAddress((void**)&at,   g_at);
    cudaGetSymbolAddress((void**)&h1,   g_h1);
    cudaGetSymbolAddress((void**)&w1,   g_w1);
    cudaGetSymbolAddress((void**)&w2,   g_w2);
    cudaGetSymbolAddress((void**)&w3,   g_w3);
    cudaGetSymbolAddress((void**)&w4,   g_w4);
    cudaGetSymbolAddress((void**)&x1,   g_x1);

    float* out_x    = (float*)d_out;
    float* edge_out = out_x + (size_t)ROWS * Dq;

    const int PG_SMEM = 2 * 2 * 128 * SROW * (int)sizeof(__half);                    // 40960
    const int FL_SMEM = (128 * QROW + 2 * 128 * QROW + 2 * 64 * VROW) * (int)sizeof(__half); // 90112
    cudaFuncSetAttribute(pg<0>, cudaFuncAttributeMaxDynamicSharedMemorySize, PG_SMEM);
    cudaFuncSetAttribute(pg<3>, cudaFuncAttributeMaxDynamicSharedMemorySize, PG_SMEM);
    cudaFuncSetAttribute(pg<4>, cudaFuncAttributeMaxDynamicSharedMemorySize, PG_SMEM);
    cudaFuncSetAttribute(pg<5>, cudaFuncAttributeMaxDynamicSharedMemorySize, PG_SMEM);
    cudaFuncSetAttribute(flash, cudaFuncAttributeMaxDynamicSharedMemorySize, FL_SMEM);

    // 0) weights -> fp16
    to_half<<<768, 256>>>(inw,  w1, 1536 * 512 / 4);
    to_half<<<256, 256>>>(outw, w2, 512 * 512 / 4);
    to_half<<<1024, 256>>>(l1w, w3, 2048 * 512 / 4);
    to_half<<<1024, 256>>>(l2w, w4, 512 * 2048 / 4);
    // 1) LN1
    ln_kernel<<<ROWS, 128>>>(x, n1w, n1b, xn);
    // 2) QKV (q,k planes; v transposed)
    pg<0><<<dim3(12, 32, 1), 256, PG_SMEM>>>(xn, w1, inb, nullptr,
                                             nullptr, q, k, vT, Dq, Dq, Dq);
    // 3) fused attention: edge_out + attn plane
    flash<<<dim3(8, BHq), 256, FL_SMEM>>>(q, k, vT, edge, edge_out, at);
    // 4) out projection + residual
    pg<3><<<dim3(4, 32, 1), 256, PG_SMEM>>>(at, w2, outb, x,
                                            x1, nullptr, nullptr, nullptr,
                                            Dq, Dq, Dq);
    // 5) LN2
    ln_kernel<<<ROWS, 128>>>(x1, n2w, n2b, xn2);
    // 6) FFN1 + GELU
    pg<4><<<dim3(16, 32, 1), 256, PG_SMEM>>>(xn2, w3, l1b, nullptr,
                                             nullptr, h1, nullptr, nullptr,
                                             Dq, Dq, Dq);
    // 7) FFN2 + residual -> final x
    pg<5><<<dim3(4, 32, 1), 256, PG_SMEM>>>(h1, w4, l2b, x1,
                                            out_x, nullptr, nullptr, nullptr,
                                            DFFq, DFFq, DFFq);
}